// round 3
// baseline (speedup 1.0000x reference)
#include <cuda_runtime.h>
#include <math.h>
#include <stdint.h>

#define N_NODE 20000
#define EMB 100
#define BATCH 512
#define SEQ 50
#define N_LAYERS 2
#define INV_TEMP 10.0f
#define W_KF 10.0f
#define TOPK 10
#define CL_WF 100.0f
#define EPSN 1e-12f

#define CL_ROWS 32
#define CL_COLS 32

// ---------------- scratch (static device globals; no runtime allocation) ----------------
__device__ float g_colsum[N_NODE];
__device__ float g_x[N_NODE*EMB];
__device__ float g_y[N_NODE*EMB];
__device__ float g_xn[N_NODE*EMB];
__device__ float g_final[N_NODE*EMB];
__device__ float g_item[N_NODE*EMB];
__device__ float g_itemn[N_NODE*EMB];
__device__ float g_s[N_NODE];
__device__ float g_amax;
__device__ float g_asum;
__device__ float g_wT[N_LAYERS*EMB*EMB];
__device__ float g_glu1T[EMB*EMB];
__device__ float g_glu2T[EMB*EMB];
__device__ float g_sess[BATCH*EMB];
__device__ float g_sessn[BATCH*EMB];

// ---------------- helpers ----------------
__device__ __forceinline__ float warp_sum(float v) {
    #pragma unroll
    for (int o = 16; o > 0; o >>= 1) v += __shfl_xor_sync(0xffffffffu, v, o);
    return v;
}

__device__ __forceinline__ void topk_insert(float (&tk)[TOPK], float v) {
    if (v > tk[TOPK-1]) {
        tk[TOPK-1] = v;
        #pragma unroll
        for (int i = TOPK-1; i > 0; --i) {
            if (tk[i] > tk[i-1]) { float tmp = tk[i-1]; tk[i-1] = tk[i]; tk[i] = tmp; }
        }
    }
}

// ---------------- init: copy embedding into x/final, zero colsum & scalar outputs ----------------
__global__ void k_init(const float* __restrict__ emb, float* __restrict__ out, int out_size) {
    int stride = gridDim.x * blockDim.x;
    int i0 = blockIdx.x * blockDim.x + threadIdx.x;
    for (int i = i0; i < N_NODE*EMB; i += stride) {
        float v = emb[i];
        g_x[i] = v;
        g_final[i] = v;
        if (i < N_NODE) g_colsum[i] = 0.0f;
    }
    if (i0 == 0) { out[0] = 0.0f; out[out_size-1] = 0.0f; }
}

// ---------------- transpose weights for coalesced reads ----------------
__global__ void k_transpose(const float* __restrict__ w_item,
                            const float* __restrict__ glu1,
                            const float* __restrict__ glu2) {
    int i = blockIdx.x * blockDim.x + threadIdx.x;
    if (i < N_LAYERS*EMB*EMB) {
        int l = i / (EMB*EMB);
        int r = i - l*(EMB*EMB);
        int j = r / EMB, k = r - j*EMB;
        // wT[l][j][k] = w_item[l][k][j]
        g_wT[l*EMB*EMB + j*EMB + k] = w_item[l*EMB*EMB + k*EMB + j];
    }
    if (i < EMB*EMB) {
        int j = i / EMB, k = i - j*EMB;
        g_glu1T[j*EMB + k] = glu1[k*EMB + j];
        g_glu2T[j*EMB + k] = glu2[k*EMB + j];
    }
}

// ---------------- column-degree sum ----------------
__global__ void k_colsum(const int* __restrict__ col, const float* __restrict__ vals, int E) {
    int e = blockIdx.x * blockDim.x + threadIdx.x;
    if (e < E) atomicAdd(&g_colsum[col[e]], vals[e]);
}

// ---------------- attention scores: s[n] = x[n].att_w + att_b (warp/node) ----------------
__global__ void k_att_score(const float* __restrict__ attw, const float* __restrict__ attb) {
    int gw = (blockIdx.x * blockDim.x + threadIdx.x) >> 5;
    int lane = threadIdx.x & 31;
    if (gw >= N_NODE) return;
    const float* xr = g_x + gw*EMB;
    float acc = 0.0f;
    for (int k = lane; k < EMB; k += 32) acc += xr[k] * attw[k];
    acc = warp_sum(acc);
    if (lane == 0) g_s[gw] = acc + attb[0];
}

// ---------------- softmax reduce over nodes (single block) ----------------
__global__ void k_softmax_reduce() {
    __shared__ float sh[1024];
    int t = threadIdx.x;
    float m = -INFINITY;
    for (int i = t; i < N_NODE; i += 1024) m = fmaxf(m, g_s[i]);
    sh[t] = m; __syncthreads();
    for (int s = 512; s > 0; s >>= 1) { if (t < s) sh[t] = fmaxf(sh[t], sh[t+s]); __syncthreads(); }
    float mx = sh[0]; __syncthreads();
    float sum = 0.0f;
    for (int i = t; i < N_NODE; i += 1024) sum += expf(g_s[i] - mx);
    sh[t] = sum; __syncthreads();
    for (int s = 512; s > 0; s >>= 1) { if (t < s) sh[t] += sh[t+s]; __syncthreads(); }
    if (t == 0) { g_amax = mx; g_asum = sh[0]; }
}

// ---------------- y = (x @ W^T) * att ; also zero xn ----------------
__global__ void k_lin_att(int layer) {
    __shared__ float xs[64*EMB];
    int base = blockIdx.x * 64;
    int t = threadIdx.x;
    int nvalid = min(64, N_NODE - base);
    for (int idx = t; idx < nvalid*EMB; idx += 256) xs[idx] = g_x[base*EMB + idx];
    __syncthreads();
    const float* WT = g_wT + layer*EMB*EMB;
    float inv = 1.0f / g_asum;
    float mx  = g_amax;
    for (int o = t; o < nvalid*EMB; o += 256) {
        int n = o / EMB, k = o - n*EMB;
        float acc = 0.0f;
        #pragma unroll 4
        for (int j = 0; j < EMB; ++j) acc += xs[n*EMB + j] * WT[j*EMB + k];
        float att = expf(g_s[base + n] - mx) * inv;
        g_y[base*EMB + o]  = acc * att;
        g_xn[base*EMB + o] = 0.0f;
    }
}

// ---------------- SpMM: xn[r] += (vals/colsum[c]) * y[c]  (warp per edge) ----------------
__global__ void k_spmm(const int* __restrict__ row, const int* __restrict__ col,
                       const float* __restrict__ vals, int E) {
    int gw = (blockIdx.x * blockDim.x + threadIdx.x) >> 5;
    int lane = threadIdx.x & 31;
    if (gw >= E) return;
    int c = col[gw], r = row[gw];
    float v = vals[gw] / g_colsum[c];
    const float* yr = g_y + (size_t)c * EMB;
    float* xr = g_xn + (size_t)r * EMB;
    for (int k = lane; k < EMB; k += 32) atomicAdd(&xr[k], v * yr[k]);
}

// ---------------- l2norm xn -> x ; final += x  (warp per node) ----------------
__global__ void k_norm_acc() {
    int gw = (blockIdx.x * blockDim.x + threadIdx.x) >> 5;
    int lane = threadIdx.x & 31;
    if (gw >= N_NODE) return;
    float* xr = g_xn + gw*EMB;
    float ss = 0.0f;
    float v[4];
    #pragma unroll
    for (int i = 0; i < 4; ++i) {
        int k = lane + 32*i;
        v[i] = (k < EMB) ? xr[k] : 0.0f;
        ss += v[i]*v[i];
    }
    ss = warp_sum(ss);
    float invn = 1.0f / fmaxf(sqrtf(ss), EPSN);
    #pragma unroll
    for (int i = 0; i < 4; ++i) {
        int k = lane + 32*i;
        if (k < EMB) {
            float nv = v[i] * invn;
            g_x[gw*EMB + k] = nv;
            g_final[gw*EMB + k] += nv;
        }
    }
}

// ---------------- item_emb = final/3 ; item_n = l2norm(item_emb) ----------------
__global__ void k_item() {
    int gw = (blockIdx.x * blockDim.x + threadIdx.x) >> 5;
    int lane = threadIdx.x & 31;
    if (gw >= N_NODE) return;
    const float inv3 = 1.0f / 3.0f;
    float ss = 0.0f;
    float v[4];
    #pragma unroll
    for (int i = 0; i < 4; ++i) {
        int k = lane + 32*i;
        v[i] = (k < EMB) ? g_final[gw*EMB + k] * inv3 : 0.0f;
        ss += v[i]*v[i];
    }
    ss = warp_sum(ss);
    float invn = 1.0f / fmaxf(sqrtf(ss), EPSN);
    #pragma unroll
    for (int i = 0; i < 4; ++i) {
        int k = lane + 32*i;
        if (k < EMB) {
            g_item[gw*EMB + k]  = v[i];
            g_itemn[gw*EMB + k] = v[i] * invn;
        }
    }
}

// ---------------- session embedding (block per session) ----------------
__global__ void k_sess(const int* __restrict__ rev, const float* __restrict__ slen,
                       const int* __restrict__ mask, const float* __restrict__ pos,
                       const float* __restrict__ w1, const float* __restrict__ w2,
                       const float* __restrict__ glu1b) {
    __shared__ float sh_seq[SEQ*EMB];
    __shared__ float sh_hs[EMB];
    __shared__ float sh_hsg[EMB];
    __shared__ float sh_nh[EMB];
    __shared__ float sh_red[128];
    int b = blockIdx.x, t = threadIdx.x;

    for (int idx = t; idx < SEQ*EMB; idx += 128) {
        int l = idx / EMB, k = idx - l*EMB;
        int id = rev[b*SEQ + l];
        sh_seq[idx] = (id == 0) ? 0.0f : g_item[(size_t)(id-1)*EMB + k];
    }
    __syncthreads();
    if (t < EMB) {
        float acc = 0.0f;
        for (int l = 0; l < SEQ; ++l) acc += sh_seq[l*EMB + t];
        sh_hs[t] = acc / slen[b];
    }
    __syncthreads();
    if (t < EMB) {
        float acc = 0.0f;
        for (int j = 0; j < EMB; ++j) acc += sh_hs[j] * g_glu2T[j*EMB + t];
        sh_hsg[t] = acc;
    }
    __syncthreads();

    float sess_k = 0.0f;
    for (int l = 0; l < SEQ; ++l) {
        if (t < EMB) {
            float acc = 0.0f;
            const float* pl = pos + l*EMB;
            for (int j = 0; j < EMB; ++j) acc += pl[j] * w1[j*EMB + t];
            for (int j = 0; j < EMB; ++j) acc += sh_seq[l*EMB + j] * w1[(EMB+j)*EMB + t];
            sh_nh[t] = tanhf(acc);
        }
        __syncthreads();
        float prod = 0.0f;
        if (t < EMB) {
            float acc = sh_hsg[t] + glu1b[t];
            for (int j = 0; j < EMB; ++j) acc += sh_nh[j] * g_glu1T[j*EMB + t];
            float g = 1.0f / (1.0f + expf(-acc));
            prod = g * w2[t];
        }
        sh_red[t] = prod;
        __syncthreads();
        for (int s = 64; s > 0; s >>= 1) {
            if (t < s) sh_red[t] += sh_red[t+s];
            __syncthreads();
        }
        float beta = sh_red[0] * (float)mask[b*SEQ + l];
        if (t < EMB) sess_k += beta * sh_seq[l*EMB + t];
        __syncthreads();
    }
    if (t < EMB) g_sess[b*EMB + t] = sess_k;
}

// ---------------- sess = W_K * l2norm(sess) (warp per session) ----------------
__global__ void k_sess_norm() {
    int gw = (blockIdx.x * blockDim.x + threadIdx.x) >> 5;
    int lane = threadIdx.x & 31;
    if (gw >= BATCH) return;
    float ss = 0.0f;
    float v[4];
    #pragma unroll
    for (int i = 0; i < 4; ++i) {
        int k = lane + 32*i;
        v[i] = (k < EMB) ? g_sess[gw*EMB + k] : 0.0f;
        ss += v[i]*v[i];
    }
    ss = warp_sum(ss);
    float sc = W_KF / fmaxf(sqrtf(ss), EPSN);
    #pragma unroll
    for (int i = 0; i < 4; ++i) {
        int k = lane + 32*i;
        if (k < EMB) g_sessn[gw*EMB + k] = v[i] * sc;
    }
}

// ---------------- scores = sessn @ itemn^T  [BATCH, N_NODE] ----------------
__global__ void k_scores(float* __restrict__ scores) {
    __shared__ __align__(16) float its[32*EMB];
    __shared__ __align__(16) float ses[64*EMB];
    int t = threadIdx.x;
    int nb = blockIdx.x * 32;   // item tile base
    int bb = blockIdx.y * 64;   // session tile base
    for (int i = t; i < 32*EMB; i += 256) its[i] = g_itemn[(size_t)nb*EMB + i];
    for (int i = t; i < 64*EMB; i += 256) ses[i] = g_sessn[(size_t)bb*EMB + i];
    __syncthreads();
    int c = t & 31;       // item col within tile
    int g = t >> 5;       // session group (8 sessions each)
    float acc[8];
    #pragma unroll
    for (int i = 0; i < 8; ++i) acc[i] = 0.0f;
    #pragma unroll 5
    for (int k4 = 0; k4 < EMB/4; ++k4) {
        float4 iv = *(const float4*)&its[c*EMB + k4*4];
        #pragma unroll
        for (int i = 0; i < 8; ++i) {
            float4 sv = *(const float4*)&ses[(g*8 + i)*EMB + k4*4];
            acc[i] += iv.x*sv.x + iv.y*sv.y + iv.z*sv.z + iv.w*sv.w;
        }
    }
    #pragma unroll
    for (int i = 0; i < 8; ++i) {
        int b = bb + g*8 + i;
        scores[(size_t)b * N_NODE + nb + c] = acc[i];
    }
}

// ---------------- loss_item: CE over scores rows ----------------
__global__ void k_loss(const float* __restrict__ scores, const int* __restrict__ tar,
                       float* __restrict__ out0) {
    __shared__ float sh[256];
    int b = blockIdx.x, t = threadIdx.x;
    const float* row = scores + (size_t)b * N_NODE;
    float m = -INFINITY;
    for (int i = t; i < N_NODE; i += 256) m = fmaxf(m, row[i]);
    sh[t] = m; __syncthreads();
    for (int s = 128; s > 0; s >>= 1) { if (t < s) sh[t] = fmaxf(sh[t], sh[t+s]); __syncthreads(); }
    float mx = sh[0]; __syncthreads();
    float sum = 0.0f;
    for (int i = t; i < N_NODE; i += 256) sum += expf(row[i] - mx);
    sh[t] = sum; __syncthreads();
    for (int s = 128; s > 0; s >>= 1) { if (t < s) sh[t] += sh[t+s]; __syncthreads(); }
    if (t == 0) {
        float lse = mx + logf(sh[0]);
        atomicAdd(out0, (lse - row[tar[b]]) * (1.0f / BATCH));
    }
}

// ---------------- cl_loss: fused N x N similarity GEMM + per-row top-10 ----------------
__global__ void k_cl(float* __restrict__ out_cl) {
    __shared__ __align__(16) float rs[CL_ROWS*EMB];   // row tile (fixed per block)
    __shared__ __align__(16) float cs[CL_COLS*EMB];   // col tile
    __shared__ float st[CL_ROWS*33];                  // dot tile (padded)
    __shared__ float mg[CL_ROWS*8*TOPK];              // merge buffer
    int t = threadIdx.x;
    int rbase = blockIdx.x * CL_ROWS;

    for (int idx = t; idx < CL_ROWS*EMB; idx += 256) rs[idx] = g_itemn[(size_t)rbase*EMB + idx];

    float tk[TOPK];
    #pragma unroll
    for (int i = 0; i < TOPK; ++i) tk[i] = -INFINITY;

    int cc  = t & 31;        // compute: col within tile
    int rg  = t >> 5;        // compute: row group (4 rows each)
    int rsc = t >> 3;        // scan: row (0..31)
    int csl = (t & 7) * 4;   // scan: col offset (4 cols)
    __syncthreads();

    for (int tile = 0; tile < N_NODE/CL_COLS; ++tile) {
        int cbase = tile * CL_COLS;
        for (int idx = t; idx < CL_COLS*EMB; idx += 256) cs[idx] = g_itemn[(size_t)cbase*EMB + idx];
        __syncthreads();

        float a0 = 0.0f, a1 = 0.0f, a2 = 0.0f, a3 = 0.0f;
        #pragma unroll 5
        for (int k4 = 0; k4 < EMB/4; ++k4) {
            float4 cv = *(const float4*)&cs[cc*EMB + k4*4];
            float4 r0 = *(const float4*)&rs[(rg*4+0)*EMB + k4*4];
            float4 r1 = *(const float4*)&rs[(rg*4+1)*EMB + k4*4];
            float4 r2 = *(const float4*)&rs[(rg*4+2)*EMB + k4*4];
            float4 r3 = *(const float4*)&rs[(rg*4+3)*EMB + k4*4];
            a0 += r0.x*cv.x + r0.y*cv.y + r0.z*cv.z + r0.w*cv.w;
            a1 += r1.x*cv.x + r1.y*cv.y + r1.z*cv.z + r1.w*cv.w;
            a2 += r2.x*cv.x + r2.y*cv.y + r2.z*cv.z + r2.w*cv.w;
            a3 += r3.x*cv.x + r3.y*cv.y + r3.z*cv.z + r3.w*cv.w;
        }
        st[(rg*4+0)*33 + cc] = a0;
        st[(rg*4+1)*33 + cc] = a1;
        st[(rg*4+2)*33 + cc] = a2;
        st[(rg*4+3)*33 + cc] = a3;
        __syncthreads();

        #pragma unroll
        for (int i = 0; i < 4; ++i) {
            float v = st[rsc*33 + csl + i] * INV_TEMP;
            topk_insert(tk, v);
        }
        __syncthreads();
    }

    // merge 8 thread-local top-10 lists per row
    #pragma unroll
    for (int i = 0; i < TOPK; ++i) mg[rsc*(8*TOPK) + (t & 7)*TOPK + i] = tk[i];
    __syncthreads();

    if (t < CL_ROWS) {
        float m[TOPK];
        #pragma unroll
        for (int i = 0; i < TOPK; ++i) m[i] = -INFINITY;
        for (int i = 0; i < 8*TOPK; ++i) topk_insert(m, mg[t*(8*TOPK) + i]);
        float se = 0.0f;
        #pragma unroll
        for (int i = 1; i < TOPK; ++i) se += expf(m[i] - m[0]);
        float clr = log1pf(se);  // logsumexp(top10) - top10[0]
        atomicAdd(out_cl, clr * (CL_WF / (float)N_NODE));
    }
}

// ---------------- launch ----------------
extern "C" void kernel_launch(void* const* d_in, const int* in_sizes, int n_in,
                              void* d_out, int out_size) {
    const float* slen  = (const float*)d_in[1];
    const int*   rev   = (const int*)d_in[2];
    const int*   mask  = (const int*)d_in[3];
    const int*   tar   = (const int*)d_in[5];
    const int*   arow  = (const int*)d_in[8];
    const int*   acol  = (const int*)d_in[9];
    const float* avals = (const float*)d_in[10];
    const float* emb   = (const float*)d_in[11];
    const float* pos   = (const float*)d_in[12];
    const float* witem = (const float*)d_in[13];
    const float* attw  = (const float*)d_in[14];
    const float* attb  = (const float*)d_in[15];
    const float* w1    = (const float*)d_in[16];
    const float* w2    = (const float*)d_in[17];
    const float* glu1  = (const float*)d_in[18];
    const float* glu1b = (const float*)d_in[19];
    const float* glu2  = (const float*)d_in[20];
    float* out = (float*)d_out;
    int E = in_sizes[8];

    k_init<<<2048, 256>>>(emb, out, out_size);
    k_transpose<<<(N_LAYERS*EMB*EMB + 255)/256, 256>>>(witem, glu1, glu2);
    k_colsum<<<(E + 255)/256, 256>>>(acol, avals, E);

    for (int l = 0; l < N_LAYERS; ++l) {
        k_att_score<<<(N_NODE*32 + 255)/256, 256>>>(attw, attb);
        k_softmax_reduce<<<1, 1024>>>();
        k_lin_att<<<(N_NODE + 63)/64, 256>>>(l);
        k_spmm<<<(E*32 + 255)/256, 256>>>(arow, acol, avals, E);
        k_norm_acc<<<(N_NODE*32 + 255)/256, 256>>>();
    }

    k_item<<<(N_NODE*32 + 255)/256, 256>>>();
    k_sess<<<BATCH, 128>>>(rev, slen, mask, pos, w1, w2, glu1b);
    k_sess_norm<<<(BATCH*32 + 255)/256, 256>>>();

    dim3 sg(N_NODE/32, BATCH/64);
    k_scores<<<sg, 256>>>(out + 1);

    k_loss<<<BATCH, 256>>>(out + 1, tar, out);
    k_cl<<<N_NODE/CL_ROWS, 256>>>(out + out_size - 1);
}

// round 4
// speedup vs baseline: 1.0017x; 1.0017x over previous
#include <cuda_runtime.h>
#include <math.h>
#include <stdint.h>

#define N_NODE 20000
#define EMB 100
#define BATCH 512
#define SEQ 50
#define N_LAYERS 2
#define INV_TEMP 10.0f
#define W_KF 10.0f
#define TOPK 10
#define CL_WF 100.0f
#define EPSN 1e-12f

#define CL_ROWS 32
#define CL_COLS 32

// ---------------- scratch (static device globals; no runtime allocation) ----------------
__device__ float g_colsum[N_NODE];
__device__ float g_x[N_NODE*EMB];
__device__ float g_y[N_NODE*EMB];
__device__ float g_xn[N_NODE*EMB];
__device__ float g_final[N_NODE*EMB];
__device__ float g_item[N_NODE*EMB];
__device__ float g_itemn[N_NODE*EMB];
__device__ float g_s[N_NODE];
__device__ float g_amax;
__device__ float g_asum;
__device__ float g_wT[N_LAYERS*EMB*EMB];
__device__ float g_glu1T[EMB*EMB];
__device__ float g_glu2T[EMB*EMB];
__device__ float g_sess[BATCH*EMB];
__device__ float g_sessn[BATCH*EMB];

// ---------------- helpers ----------------
__device__ __forceinline__ float warp_sum(float v) {
    #pragma unroll
    for (int o = 16; o > 0; o >>= 1) v += __shfl_xor_sync(0xffffffffu, v, o);
    return v;
}

__device__ __forceinline__ void topk_insert(float (&tk)[TOPK], float v) {
    if (v > tk[TOPK-1]) {
        tk[TOPK-1] = v;
        #pragma unroll
        for (int i = TOPK-1; i > 0; --i) {
            if (tk[i] > tk[i-1]) { float tmp = tk[i-1]; tk[i-1] = tk[i]; tk[i] = tmp; }
        }
    }
}

// ---------------- init: copy embedding into x/final, zero colsum & scalar outputs ----------------
__global__ void k_init(const float* __restrict__ emb, float* __restrict__ out, int out_size) {
    int stride = gridDim.x * blockDim.x;
    int i0 = blockIdx.x * blockDim.x + threadIdx.x;
    for (int i = i0; i < N_NODE*EMB; i += stride) {
        float v = emb[i];
        g_x[i] = v;
        g_final[i] = v;
        if (i < N_NODE) g_colsum[i] = 0.0f;
    }
    if (i0 == 0) { out[0] = 0.0f; out[out_size-1] = 0.0f; }
}

// ---------------- transpose weights for coalesced reads ----------------
__global__ void k_transpose(const float* __restrict__ w_item,
                            const float* __restrict__ glu1,
                            const float* __restrict__ glu2) {
    int i = blockIdx.x * blockDim.x + threadIdx.x;
    if (i < N_LAYERS*EMB*EMB) {
        int l = i / (EMB*EMB);
        int r = i - l*(EMB*EMB);
        int j = r / EMB, k = r - j*EMB;
        // wT[l][j][k] = w_item[l][k][j]
        g_wT[l*EMB*EMB + j*EMB + k] = w_item[l*EMB*EMB + k*EMB + j];
    }
    if (i < EMB*EMB) {
        int j = i / EMB, k = i - j*EMB;
        g_glu1T[j*EMB + k] = glu1[k*EMB + j];
        g_glu2T[j*EMB + k] = glu2[k*EMB + j];
    }
}

// ---------------- column-degree sum ----------------
__global__ void k_colsum(const int* __restrict__ col, const float* __restrict__ vals, int E) {
    int e = blockIdx.x * blockDim.x + threadIdx.x;
    if (e < E) atomicAdd(&g_colsum[col[e]], vals[e]);
}

// ---------------- attention scores: s[n] = x[n].att_w + att_b (warp/node) ----------------
__global__ void k_att_score(const float* __restrict__ attw, const float* __restrict__ attb) {
    int gw = (blockIdx.x * blockDim.x + threadIdx.x) >> 5;
    int lane = threadIdx.x & 31;
    if (gw >= N_NODE) return;
    const float* xr = g_x + gw*EMB;
    float acc = 0.0f;
    for (int k = lane; k < EMB; k += 32) acc += xr[k] * attw[k];
    acc = warp_sum(acc);
    if (lane == 0) g_s[gw] = acc + attb[0];
}

// ---------------- softmax reduce over nodes (single block) ----------------
__global__ void k_softmax_reduce() {
    __shared__ float sh[1024];
    int t = threadIdx.x;
    float m = -INFINITY;
    for (int i = t; i < N_NODE; i += 1024) m = fmaxf(m, g_s[i]);
    sh[t] = m; __syncthreads();
    for (int s = 512; s > 0; s >>= 1) { if (t < s) sh[t] = fmaxf(sh[t], sh[t+s]); __syncthreads(); }
    float mx = sh[0]; __syncthreads();
    float sum = 0.0f;
    for (int i = t; i < N_NODE; i += 1024) sum += expf(g_s[i] - mx);
    sh[t] = sum; __syncthreads();
    for (int s = 512; s > 0; s >>= 1) { if (t < s) sh[t] += sh[t+s]; __syncthreads(); }
    if (t == 0) { g_amax = mx; g_asum = sh[0]; }
}

// ---------------- y = (x @ W^T) * att ; also zero xn ----------------
__global__ void k_lin_att(int layer) {
    __shared__ float xs[64*EMB];
    int base = blockIdx.x * 64;
    int t = threadIdx.x;
    int nvalid = min(64, N_NODE - base);
    for (int idx = t; idx < nvalid*EMB; idx += 256) xs[idx] = g_x[base*EMB + idx];
    __syncthreads();
    const float* WT = g_wT + layer*EMB*EMB;
    float inv = 1.0f / g_asum;
    float mx  = g_amax;
    for (int o = t; o < nvalid*EMB; o += 256) {
        int n = o / EMB, k = o - n*EMB;
        float acc = 0.0f;
        #pragma unroll 4
        for (int j = 0; j < EMB; ++j) acc += xs[n*EMB + j] * WT[j*EMB + k];
        float att = expf(g_s[base + n] - mx) * inv;
        g_y[base*EMB + o]  = acc * att;
        g_xn[base*EMB + o] = 0.0f;
    }
}

// ---------------- SpMM: xn[r] += (vals/colsum[c]) * y[c]  (warp per edge) ----------------
__global__ void k_spmm(const int* __restrict__ row, const int* __restrict__ col,
                       const float* __restrict__ vals, int E) {
    int gw = (blockIdx.x * blockDim.x + threadIdx.x) >> 5;
    int lane = threadIdx.x & 31;
    if (gw >= E) return;
    int c = col[gw], r = row[gw];
    float v = vals[gw] / g_colsum[c];
    const float* yr = g_y + (size_t)c * EMB;
    float* xr = g_xn + (size_t)r * EMB;
    for (int k = lane; k < EMB; k += 32) atomicAdd(&xr[k], v * yr[k]);
}

// ---------------- l2norm xn -> x ; final += x  (warp per node) ----------------
__global__ void k_norm_acc() {
    int gw = (blockIdx.x * blockDim.x + threadIdx.x) >> 5;
    int lane = threadIdx.x & 31;
    if (gw >= N_NODE) return;
    float* xr = g_xn + gw*EMB;
    float ss = 0.0f;
    float v[4];
    #pragma unroll
    for (int i = 0; i < 4; ++i) {
        int k = lane + 32*i;
        v[i] = (k < EMB) ? xr[k] : 0.0f;
        ss += v[i]*v[i];
    }
    ss = warp_sum(ss);
    float invn = 1.0f / fmaxf(sqrtf(ss), EPSN);
    #pragma unroll
    for (int i = 0; i < 4; ++i) {
        int k = lane + 32*i;
        if (k < EMB) {
            float nv = v[i] * invn;
            g_x[gw*EMB + k] = nv;
            g_final[gw*EMB + k] += nv;
        }
    }
}

// ---------------- item_emb = final/3 ; item_n = l2norm(item_emb) ----------------
__global__ void k_item() {
    int gw = (blockIdx.x * blockDim.x + threadIdx.x) >> 5;
    int lane = threadIdx.x & 31;
    if (gw >= N_NODE) return;
    const float inv3 = 1.0f / 3.0f;
    float ss = 0.0f;
    float v[4];
    #pragma unroll
    for (int i = 0; i < 4; ++i) {
        int k = lane + 32*i;
        v[i] = (k < EMB) ? g_final[gw*EMB + k] * inv3 : 0.0f;
        ss += v[i]*v[i];
    }
    ss = warp_sum(ss);
    float invn = 1.0f / fmaxf(sqrtf(ss), EPSN);
    #pragma unroll
    for (int i = 0; i < 4; ++i) {
        int k = lane + 32*i;
        if (k < EMB) {
            g_item[gw*EMB + k]  = v[i];
            g_itemn[gw*EMB + k] = v[i] * invn;
        }
    }
}

// ---------------- session embedding (block per session) ----------------
__global__ void k_sess(const int* __restrict__ rev, const float* __restrict__ slen,
                       const int* __restrict__ mask, const float* __restrict__ pos,
                       const float* __restrict__ w1, const float* __restrict__ w2,
                       const float* __restrict__ glu1b) {
    __shared__ float sh_seq[SEQ*EMB];
    __shared__ float sh_hs[EMB];
    __shared__ float sh_hsg[EMB];
    __shared__ float sh_nh[EMB];
    __shared__ float sh_red[128];
    int b = blockIdx.x, t = threadIdx.x;

    for (int idx = t; idx < SEQ*EMB; idx += 128) {
        int l = idx / EMB, k = idx - l*EMB;
        int id = rev[b*SEQ + l];
        sh_seq[idx] = (id == 0) ? 0.0f : g_item[(size_t)(id-1)*EMB + k];
    }
    __syncthreads();
    if (t < EMB) {
        float acc = 0.0f;
        for (int l = 0; l < SEQ; ++l) acc += sh_seq[l*EMB + t];
        sh_hs[t] = acc / slen[b];
    }
    __syncthreads();
    if (t < EMB) {
        float acc = 0.0f;
        for (int j = 0; j < EMB; ++j) acc += sh_hs[j] * g_glu2T[j*EMB + t];
        sh_hsg[t] = acc;
    }
    __syncthreads();

    float sess_k = 0.0f;
    for (int l = 0; l < SEQ; ++l) {
        if (t < EMB) {
            float acc = 0.0f;
            const float* pl = pos + l*EMB;
            for (int j = 0; j < EMB; ++j) acc += pl[j] * w1[j*EMB + t];
            for (int j = 0; j < EMB; ++j) acc += sh_seq[l*EMB + j] * w1[(EMB+j)*EMB + t];
            sh_nh[t] = tanhf(acc);
        }
        __syncthreads();
        float prod = 0.0f;
        if (t < EMB) {
            float acc = sh_hsg[t] + glu1b[t];
            for (int j = 0; j < EMB; ++j) acc += sh_nh[j] * g_glu1T[j*EMB + t];
            float g = 1.0f / (1.0f + expf(-acc));
            prod = g * w2[t];
        }
        sh_red[t] = prod;
        __syncthreads();
        for (int s = 64; s > 0; s >>= 1) {
            if (t < s) sh_red[t] += sh_red[t+s];
            __syncthreads();
        }
        float beta = sh_red[0] * (float)mask[b*SEQ + l];
        if (t < EMB) sess_k += beta * sh_seq[l*EMB + t];
        __syncthreads();
    }
    if (t < EMB) g_sess[b*EMB + t] = sess_k;
}

// ---------------- sess = W_K * l2norm(sess) (warp per session) ----------------
__global__ void k_sess_norm() {
    int gw = (blockIdx.x * blockDim.x + threadIdx.x) >> 5;
    int lane = threadIdx.x & 31;
    if (gw >= BATCH) return;
    float ss = 0.0f;
    float v[4];
    #pragma unroll
    for (int i = 0; i < 4; ++i) {
        int k = lane + 32*i;
        v[i] = (k < EMB) ? g_sess[gw*EMB + k] : 0.0f;
        ss += v[i]*v[i];
    }
    ss = warp_sum(ss);
    float sc = W_KF / fmaxf(sqrtf(ss), EPSN);
    #pragma unroll
    for (int i = 0; i < 4; ++i) {
        int k = lane + 32*i;
        if (k < EMB) g_sessn[gw*EMB + k] = v[i] * sc;
    }
}

// ---------------- scores = sessn @ itemn^T  [BATCH, N_NODE] ----------------
__global__ void k_scores(float* __restrict__ scores) {
    __shared__ __align__(16) float its[32*EMB];
    __shared__ __align__(16) float ses[64*EMB];
    int t = threadIdx.x;
    int nb = blockIdx.x * 32;   // item tile base
    int bb = blockIdx.y * 64;   // session tile base
    for (int i = t; i < 32*EMB; i += 256) its[i] = g_itemn[(size_t)nb*EMB + i];
    for (int i = t; i < 64*EMB; i += 256) ses[i] = g_sessn[(size_t)bb*EMB + i];
    __syncthreads();
    int c = t & 31;       // item col within tile
    int g = t >> 5;       // session group (8 sessions each)
    float acc[8];
    #pragma unroll
    for (int i = 0; i < 8; ++i) acc[i] = 0.0f;
    #pragma unroll 5
    for (int k4 = 0; k4 < EMB/4; ++k4) {
        float4 iv = *(const float4*)&its[c*EMB + k4*4];
        #pragma unroll
        for (int i = 0; i < 8; ++i) {
            float4 sv = *(const float4*)&ses[(g*8 + i)*EMB + k4*4];
            acc[i] += iv.x*sv.x + iv.y*sv.y + iv.z*sv.z + iv.w*sv.w;
        }
    }
    #pragma unroll
    for (int i = 0; i < 8; ++i) {
        int b = bb + g*8 + i;
        scores[(size_t)b * N_NODE + nb + c] = acc[i];
    }
}

// ---------------- loss_item: CE over scores rows ----------------
__global__ void k_loss(const float* __restrict__ scores, const int* __restrict__ tar,
                       float* __restrict__ out0) {
    __shared__ float sh[256];
    int b = blockIdx.x, t = threadIdx.x;
    const float* row = scores + (size_t)b * N_NODE;
    float m = -INFINITY;
    for (int i = t; i < N_NODE; i += 256) m = fmaxf(m, row[i]);
    sh[t] = m; __syncthreads();
    for (int s = 128; s > 0; s >>= 1) { if (t < s) sh[t] = fmaxf(sh[t], sh[t+s]); __syncthreads(); }
    float mx = sh[0]; __syncthreads();
    float sum = 0.0f;
    for (int i = t; i < N_NODE; i += 256) sum += expf(row[i] - mx);
    sh[t] = sum; __syncthreads();
    for (int s = 128; s > 0; s >>= 1) { if (t < s) sh[t] += sh[t+s]; __syncthreads(); }
    if (t == 0) {
        float lse = mx + logf(sh[0]);
        atomicAdd(out0, (lse - row[tar[b]]) * (1.0f / BATCH));
    }
}

// ---------------- cl_loss: fused N x N similarity GEMM + per-row top-10 ----------------
__global__ void k_cl(float* __restrict__ out_cl) {
    __shared__ __align__(16) float rs[CL_ROWS*EMB];   // row tile (fixed per block)
    __shared__ __align__(16) float cs[CL_COLS*EMB];   // col tile
    __shared__ float st[CL_ROWS*33];                  // dot tile (padded)
    __shared__ float mg[CL_ROWS*8*TOPK];              // merge buffer
    int t = threadIdx.x;
    int rbase = blockIdx.x * CL_ROWS;

    for (int idx = t; idx < CL_ROWS*EMB; idx += 256) rs[idx] = g_itemn[(size_t)rbase*EMB + idx];

    float tk[TOPK];
    #pragma unroll
    for (int i = 0; i < TOPK; ++i) tk[i] = -INFINITY;

    int cc  = t & 31;        // compute: col within tile
    int rg  = t >> 5;        // compute: row group (4 rows each)
    int rsc = t >> 3;        // scan: row (0..31)
    int csl = (t & 7) * 4;   // scan: col offset (4 cols)
    __syncthreads();

    for (int tile = 0; tile < N_NODE/CL_COLS; ++tile) {
        int cbase = tile * CL_COLS;
        for (int idx = t; idx < CL_COLS*EMB; idx += 256) cs[idx] = g_itemn[(size_t)cbase*EMB + idx];
        __syncthreads();

        float a0 = 0.0f, a1 = 0.0f, a2 = 0.0f, a3 = 0.0f;
        #pragma unroll 5
        for (int k4 = 0; k4 < EMB/4; ++k4) {
            float4 cv = *(const float4*)&cs[cc*EMB + k4*4];
            float4 r0 = *(const float4*)&rs[(rg*4+0)*EMB + k4*4];
            float4 r1 = *(const float4*)&rs[(rg*4+1)*EMB + k4*4];
            float4 r2 = *(const float4*)&rs[(rg*4+2)*EMB + k4*4];
            float4 r3 = *(const float4*)&rs[(rg*4+3)*EMB + k4*4];
            a0 += r0.x*cv.x + r0.y*cv.y + r0.z*cv.z + r0.w*cv.w;
            a1 += r1.x*cv.x + r1.y*cv.y + r1.z*cv.z + r1.w*cv.w;
            a2 += r2.x*cv.x + r2.y*cv.y + r2.z*cv.z + r2.w*cv.w;
            a3 += r3.x*cv.x + r3.y*cv.y + r3.z*cv.z + r3.w*cv.w;
        }
        st[(rg*4+0)*33 + cc] = a0;
        st[(rg*4+1)*33 + cc] = a1;
        st[(rg*4+2)*33 + cc] = a2;
        st[(rg*4+3)*33 + cc] = a3;
        __syncthreads();

        #pragma unroll
        for (int i = 0; i < 4; ++i) {
            float v = st[rsc*33 + csl + i] * INV_TEMP;
            topk_insert(tk, v);
        }
        __syncthreads();
    }

    // merge 8 thread-local top-10 lists per row
    #pragma unroll
    for (int i = 0; i < TOPK; ++i) mg[rsc*(8*TOPK) + (t & 7)*TOPK + i] = tk[i];
    __syncthreads();

    if (t < CL_ROWS) {
        float m[TOPK];
        #pragma unroll
        for (int i = 0; i < TOPK; ++i) m[i] = -INFINITY;
        for (int i = 0; i < 8*TOPK; ++i) topk_insert(m, mg[t*(8*TOPK) + i]);
        float se = 0.0f;
        #pragma unroll
        for (int i = 1; i < TOPK; ++i) se += expf(m[i] - m[0]);
        float clr = log1pf(se);  // logsumexp(top10) - top10[0]
        atomicAdd(out_cl, clr * (CL_WF / (float)N_NODE));
    }
}

// ---------------- launch ----------------
extern "C" void kernel_launch(void* const* d_in, const int* in_sizes, int n_in,
                              void* d_out, int out_size) {
    const float* slen  = (const float*)d_in[1];
    const int*   rev   = (const int*)d_in[2];
    const int*   mask  = (const int*)d_in[3];
    const int*   tar   = (const int*)d_in[5];
    const int*   arow  = (const int*)d_in[8];
    const int*   acol  = (const int*)d_in[9];
    const float* avals = (const float*)d_in[10];
    const float* emb   = (const float*)d_in[11];
    const float* pos   = (const float*)d_in[12];
    const float* witem = (const float*)d_in[13];
    const float* attw  = (const float*)d_in[14];
    const float* attb  = (const float*)d_in[15];
    const float* w1    = (const float*)d_in[16];
    const float* w2    = (const float*)d_in[17];
    const float* glu1  = (const float*)d_in[18];
    const float* glu1b = (const float*)d_in[19];
    const float* glu2  = (const float*)d_in[20];
    float* out = (float*)d_out;
    int E = in_sizes[8];

    k_init<<<2048, 256>>>(emb, out, out_size);
    k_transpose<<<(N_LAYERS*EMB*EMB + 255)/256, 256>>>(witem, glu1, glu2);
    k_colsum<<<(E + 255)/256, 256>>>(acol, avals, E);

    for (int l = 0; l < N_LAYERS; ++l) {
        k_att_score<<<(N_NODE*32 + 255)/256, 256>>>(attw, attb);
        k_softmax_reduce<<<1, 1024>>>();
        k_lin_att<<<(N_NODE + 63)/64, 256>>>(l);
        k_spmm<<<(E*32 + 255)/256, 256>>>(arow, acol, avals, E);
        k_norm_acc<<<(N_NODE*32 + 255)/256, 256>>>();
    }

    k_item<<<(N_NODE*32 + 255)/256, 256>>>();
    k_sess<<<BATCH, 128>>>(rev, slen, mask, pos, w1, w2, glu1b);
    k_sess_norm<<<(BATCH*32 + 255)/256, 256>>>();

    dim3 sg(N_NODE/32, BATCH/64);
    k_scores<<<sg, 256>>>(out + 1);

    k_loss<<<BATCH, 256>>>(out + 1, tar, out);
    k_cl<<<N_NODE/CL_ROWS, 256>>>(out + out_size - 1);
}

// round 5
// speedup vs baseline: 2.8740x; 2.8691x over previous
#include <cuda_runtime.h>
#include <cuda_bf16.h>
#include <math.h>
#include <stdint.h>

#define N_NODE 20000
#define EMB 100
#define BATCH 512
#define SEQ 50
#define N_LAYERS 2
#define INV_TEMP 10.0f
#define W_KF 10.0f
#define TOPK 10
#define CL_WF 100.0f
#define EPSN 1e-12f

// tensor-core cl gemm tiling
#define CLM 128                 // rows per block
#define CLN 64                  // cols per tile
#define KPAD 112                // EMB padded to 7*16
#define KC 7                    // k-chunks of 16
#define NBLK 157                // ceil(20000/128)
#define ROWS_PAD (NBLK*CLM)     // 20096
#define NTILES 313              // ceil(20000/64)
#define BROW 120                // smem row stride in halves (240B, conflict-free)

// ---------------- scratch (static device globals; no runtime allocation) ----------------
__device__ float g_colsum[N_NODE];
__device__ float g_x[N_NODE*EMB];
__device__ float g_y[N_NODE*EMB];
__device__ float g_xn[N_NODE*EMB];
__device__ float g_final[N_NODE*EMB];
__device__ float g_item[N_NODE*EMB];
__device__ float g_itemn[N_NODE*EMB];
__device__ float g_s[N_NODE];
__device__ float g_amax;
__device__ float g_asum;
__device__ float g_wT[N_LAYERS*EMB*EMB];
__device__ float g_glu1T[EMB*EMB];
__device__ float g_glu2T[EMB*EMB];
__device__ float g_sess[BATCH*EMB];
__device__ float g_sessn[BATCH*EMB];
__device__ float g_posw[SEQ*EMB];
__device__ __align__(16) __nv_bfloat16 g_bf16[ROWS_PAD*KPAD];

// ---------------- helpers ----------------
__device__ __forceinline__ float warp_sum(float v) {
    #pragma unroll
    for (int o = 16; o > 0; o >>= 1) v += __shfl_xor_sync(0xffffffffu, v, o);
    return v;
}

__device__ __forceinline__ void topk_insert(float (&tk)[TOPK], float v) {
    if (v > tk[TOPK-1]) {
        tk[TOPK-1] = v;
        #pragma unroll
        for (int i = TOPK-1; i > 0; --i) {
            if (tk[i] > tk[i-1]) { float tmp = tk[i-1]; tk[i-1] = tk[i]; tk[i] = tmp; }
        }
    }
}

// ---------------- init ----------------
__global__ void k_init(const float* __restrict__ emb, float* __restrict__ out, int out_size) {
    int stride = gridDim.x * blockDim.x;
    int i0 = blockIdx.x * blockDim.x + threadIdx.x;
    for (int i = i0; i < N_NODE*EMB; i += stride) {
        float v = emb[i];
        g_x[i] = v;
        g_final[i] = v;
        if (i < N_NODE) g_colsum[i] = 0.0f;
    }
    if (i0 == 0) { out[0] = 0.0f; out[out_size-1] = 0.0f; }
}

// ---------------- transpose weights ----------------
__global__ void k_transpose(const float* __restrict__ w_item,
                            const float* __restrict__ glu1,
                            const float* __restrict__ glu2) {
    int i = blockIdx.x * blockDim.x + threadIdx.x;
    if (i < N_LAYERS*EMB*EMB) {
        int l = i / (EMB*EMB);
        int r = i - l*(EMB*EMB);
        int j = r / EMB, k = r - j*EMB;
        g_wT[l*EMB*EMB + j*EMB + k] = w_item[l*EMB*EMB + k*EMB + j];
    }
    if (i < EMB*EMB) {
        int j = i / EMB, k = i - j*EMB;
        g_glu1T[j*EMB + k] = glu1[k*EMB + j];
        g_glu2T[j*EMB + k] = glu2[k*EMB + j];
    }
}

// ---------------- posW[l][t] = sum_j pos[l][j] * w1[j][t]  (session-invariant) ----------------
__global__ void k_posw(const float* __restrict__ pos, const float* __restrict__ w1) {
    int l = blockIdx.x, t = threadIdx.x;
    if (t < EMB) {
        float acc = 0.0f;
        for (int j = 0; j < EMB; ++j) acc += pos[l*EMB + j] * w1[j*EMB + t];
        g_posw[l*EMB + t] = acc;
    }
}

// ---------------- column-degree sum ----------------
__global__ void k_colsum(const int* __restrict__ col, const float* __restrict__ vals, int E) {
    int e = blockIdx.x * blockDim.x + threadIdx.x;
    if (e < E) atomicAdd(&g_colsum[col[e]], vals[e]);
}

// ---------------- attention scores ----------------
__global__ void k_att_score(const float* __restrict__ attw, const float* __restrict__ attb) {
    int gw = (blockIdx.x * blockDim.x + threadIdx.x) >> 5;
    int lane = threadIdx.x & 31;
    if (gw >= N_NODE) return;
    const float* xr = g_x + gw*EMB;
    float acc = 0.0f;
    for (int k = lane; k < EMB; k += 32) acc += xr[k] * attw[k];
    acc = warp_sum(acc);
    if (lane == 0) g_s[gw] = acc + attb[0];
}

// ---------------- softmax reduce over nodes ----------------
__global__ void k_softmax_reduce() {
    __shared__ float sh[1024];
    int t = threadIdx.x;
    float m = -INFINITY;
    for (int i = t; i < N_NODE; i += 1024) m = fmaxf(m, g_s[i]);
    sh[t] = m; __syncthreads();
    for (int s = 512; s > 0; s >>= 1) { if (t < s) sh[t] = fmaxf(sh[t], sh[t+s]); __syncthreads(); }
    float mx = sh[0]; __syncthreads();
    float sum = 0.0f;
    for (int i = t; i < N_NODE; i += 1024) sum += expf(g_s[i] - mx);
    sh[t] = sum; __syncthreads();
    for (int s = 512; s > 0; s >>= 1) { if (t < s) sh[t] += sh[t+s]; __syncthreads(); }
    if (t == 0) { g_amax = mx; g_asum = sh[0]; }
}

// ---------------- y = (x @ W^T) * att ; zero xn ----------------
__global__ void k_lin_att(int layer) {
    __shared__ float xs[64*EMB];
    int base = blockIdx.x * 64;
    int t = threadIdx.x;
    int nvalid = min(64, N_NODE - base);
    for (int idx = t; idx < nvalid*EMB; idx += 256) xs[idx] = g_x[base*EMB + idx];
    __syncthreads();
    const float* WT = g_wT + layer*EMB*EMB;
    float inv = 1.0f / g_asum;
    float mx  = g_amax;
    for (int o = t; o < nvalid*EMB; o += 256) {
        int n = o / EMB, k = o - n*EMB;
        float acc = 0.0f;
        #pragma unroll 4
        for (int j = 0; j < EMB; ++j) acc += xs[n*EMB + j] * WT[j*EMB + k];
        float att = expf(g_s[base + n] - mx) * inv;
        g_y[base*EMB + o]  = acc * att;
        g_xn[base*EMB + o] = 0.0f;
    }
}

// ---------------- SpMM (warp per edge) ----------------
__global__ void k_spmm(const int* __restrict__ row, const int* __restrict__ col,
                       const float* __restrict__ vals, int E) {
    int gw = (blockIdx.x * blockDim.x + threadIdx.x) >> 5;
    int lane = threadIdx.x & 31;
    if (gw >= E) return;
    int c = col[gw], r = row[gw];
    float v = vals[gw] / g_colsum[c];
    const float* yr = g_y + (size_t)c * EMB;
    float* xr = g_xn + (size_t)r * EMB;
    for (int k = lane; k < EMB; k += 32) atomicAdd(&xr[k], v * yr[k]);
}

// ---------------- l2norm xn -> x ; final += x ----------------
__global__ void k_norm_acc() {
    int gw = (blockIdx.x * blockDim.x + threadIdx.x) >> 5;
    int lane = threadIdx.x & 31;
    if (gw >= N_NODE) return;
    float* xr = g_xn + gw*EMB;
    float ss = 0.0f;
    float v[4];
    #pragma unroll
    for (int i = 0; i < 4; ++i) {
        int k = lane + 32*i;
        v[i] = (k < EMB) ? xr[k] : 0.0f;
        ss += v[i]*v[i];
    }
    ss = warp_sum(ss);
    float invn = 1.0f / fmaxf(sqrtf(ss), EPSN);
    #pragma unroll
    for (int i = 0; i < 4; ++i) {
        int k = lane + 32*i;
        if (k < EMB) {
            float nv = v[i] * invn;
            g_x[gw*EMB + k] = nv;
            g_final[gw*EMB + k] += nv;
        }
    }
}

// ---------------- item_emb = final/3 ; item_n = l2norm ----------------
__global__ void k_item() {
    int gw = (blockIdx.x * blockDim.x + threadIdx.x) >> 5;
    int lane = threadIdx.x & 31;
    if (gw >= N_NODE) return;
    const float inv3 = 1.0f / 3.0f;
    float ss = 0.0f;
    float v[4];
    #pragma unroll
    for (int i = 0; i < 4; ++i) {
        int k = lane + 32*i;
        v[i] = (k < EMB) ? g_final[gw*EMB + k] * inv3 : 0.0f;
        ss += v[i]*v[i];
    }
    ss = warp_sum(ss);
    float invn = 1.0f / fmaxf(sqrtf(ss), EPSN);
    #pragma unroll
    for (int i = 0; i < 4; ++i) {
        int k = lane + 32*i;
        if (k < EMB) {
            g_item[gw*EMB + k]  = v[i];
            g_itemn[gw*EMB + k] = v[i] * invn;
        }
    }
}

// ---------------- itemn -> bf16 padded [ROWS_PAD, KPAD] ----------------
__global__ void k_bf16cvt() {
    int i = blockIdx.x * blockDim.x + threadIdx.x;
    if (i >= ROWS_PAD*KPAD) return;
    int node = i / KPAD, k = i - node*KPAD;
    float v = (node < N_NODE && k < EMB) ? g_itemn[node*EMB + k] : 0.0f;
    g_bf16[i] = __float2bfloat16(v);
}

// ---------------- session embedding (block per session) ----------------
__global__ void k_sess(const int* __restrict__ rev, const float* __restrict__ slen,
                       const int* __restrict__ mask, const float* __restrict__ w1,
                       const float* __restrict__ w2, const float* __restrict__ glu1b) {
    __shared__ float sh_seq[SEQ*EMB];
    __shared__ float sh_hs[EMB];
    __shared__ float sh_hsg[EMB];
    __shared__ float sh_nh[EMB];
    __shared__ float sh_red[128];
    int b = blockIdx.x, t = threadIdx.x;

    for (int idx = t; idx < SEQ*EMB; idx += 128) {
        int l = idx / EMB, k = idx - l*EMB;
        int id = rev[b*SEQ + l];
        sh_seq[idx] = (id == 0) ? 0.0f : g_item[(size_t)(id-1)*EMB + k];
    }
    __syncthreads();
    if (t < EMB) {
        float acc = 0.0f;
        for (int l = 0; l < SEQ; ++l) acc += sh_seq[l*EMB + t];
        sh_hs[t] = acc / slen[b];
    }
    __syncthreads();
    if (t < EMB) {
        float acc = 0.0f;
        for (int j = 0; j < EMB; ++j) acc += sh_hs[j] * g_glu2T[j*EMB + t];
        sh_hsg[t] = acc;
    }
    __syncthreads();

    float sess_k = 0.0f;
    for (int l = 0; l < SEQ; ++l) {
        if (t < EMB) {
            float acc = g_posw[l*EMB + t];
            for (int j = 0; j < EMB; ++j) acc += sh_seq[l*EMB + j] * w1[(EMB+j)*EMB + t];
            sh_nh[t] = tanhf(acc);
        }
        __syncthreads();
        float prod = 0.0f;
        if (t < EMB) {
            float acc = sh_hsg[t] + glu1b[t];
            for (int j = 0; j < EMB; ++j) acc += sh_nh[j] * g_glu1T[j*EMB + t];
            float g = 1.0f / (1.0f + expf(-acc));
            prod = g * w2[t];
        }
        sh_red[t] = prod;
        __syncthreads();
        for (int s = 64; s > 0; s >>= 1) {
            if (t < s) sh_red[t] += sh_red[t+s];
            __syncthreads();
        }
        float beta = sh_red[0] * (float)mask[b*SEQ + l];
        if (t < EMB) sess_k += beta * sh_seq[l*EMB + t];
        __syncthreads();
    }
    if (t < EMB) g_sess[b*EMB + t] = sess_k;
}

// ---------------- sess = W_K * l2norm(sess) ----------------
__global__ void k_sess_norm() {
    int gw = (blockIdx.x * blockDim.x + threadIdx.x) >> 5;
    int lane = threadIdx.x & 31;
    if (gw >= BATCH) return;
    float ss = 0.0f;
    float v[4];
    #pragma unroll
    for (int i = 0; i < 4; ++i) {
        int k = lane + 32*i;
        v[i] = (k < EMB) ? g_sess[gw*EMB + k] : 0.0f;
        ss += v[i]*v[i];
    }
    ss = warp_sum(ss);
    float sc = W_KF / fmaxf(sqrtf(ss), EPSN);
    #pragma unroll
    for (int i = 0; i < 4; ++i) {
        int k = lane + 32*i;
        if (k < EMB) g_sessn[gw*EMB + k] = v[i] * sc;
    }
}

// ---------------- scores = sessn @ itemn^T (fp32, padded-stride smem) ----------------
#define ITS_STRIDE 104
__global__ void k_scores(float* __restrict__ scores) {
    __shared__ __align__(16) float its[32*ITS_STRIDE];
    __shared__ __align__(16) float ses[64*EMB];
    int t = threadIdx.x;
    int nb = blockIdx.x * 32;
    int bb = blockIdx.y * 64;
    for (int i = t; i < 32*EMB; i += 256) {
        int r = i / EMB, k = i - r*EMB;
        its[r*ITS_STRIDE + k] = g_itemn[(size_t)nb*EMB + i];
    }
    for (int i = t; i < 64*EMB; i += 256) ses[i] = g_sessn[(size_t)bb*EMB + i];
    __syncthreads();
    int c = t & 31;
    int g = t >> 5;
    float acc[8];
    #pragma unroll
    for (int i = 0; i < 8; ++i) acc[i] = 0.0f;
    #pragma unroll 5
    for (int k4 = 0; k4 < EMB/4; ++k4) {
        float4 iv = *(const float4*)&its[c*ITS_STRIDE + k4*4];
        #pragma unroll
        for (int i = 0; i < 8; ++i) {
            float4 sv = *(const float4*)&ses[(g*8 + i)*EMB + k4*4];
            acc[i] += iv.x*sv.x + iv.y*sv.y + iv.z*sv.z + iv.w*sv.w;
        }
    }
    #pragma unroll
    for (int i = 0; i < 8; ++i) {
        int b = bb + g*8 + i;
        scores[(size_t)b * N_NODE + nb + c] = acc[i];
    }
}

// ---------------- loss_item: CE over score rows ----------------
__global__ void k_loss(const float* __restrict__ scores, const int* __restrict__ tar,
                       float* __restrict__ out0) {
    __shared__ float sh[256];
    int b = blockIdx.x, t = threadIdx.x;
    const float* row = scores + (size_t)b * N_NODE;
    float m = -INFINITY;
    for (int i = t; i < N_NODE; i += 256) m = fmaxf(m, row[i]);
    sh[t] = m; __syncthreads();
    for (int s = 128; s > 0; s >>= 1) { if (t < s) sh[t] = fmaxf(sh[t], sh[t+s]); __syncthreads(); }
    float mx = sh[0]; __syncthreads();
    float sum = 0.0f;
    for (int i = t; i < N_NODE; i += 256) sum += expf(row[i] - mx);
    sh[t] = sum; __syncthreads();
    for (int s = 128; s > 0; s >>= 1) { if (t < s) sh[t] += sh[t+s]; __syncthreads(); }
    if (t == 0) {
        float lse = mx + logf(sh[0]);
        atomicAdd(out0, (lse - row[tar[b]]) * (1.0f / BATCH));
    }
}

// ---------------- cl_loss: bf16 tensor-core N x N GEMM fused with per-row top-10 ----------------
// Block: 256 threads = 8 warps. Each warp owns 16 rows; A fragments persist in registers.
// Col tiles of 64 double-buffered via cp.async. Epilogue merges 4 thread-local top-10s per row.
__global__ __launch_bounds__(256) void k_cl_tc(float* __restrict__ out_cl) {
    __shared__ __align__(16) char smraw[2*CLN*BROW*2];  // 30720 B (A stage / B dbl-buf / merge)
    uint32_t sbase = (uint32_t)__cvta_generic_to_shared(smraw);
    int t = threadIdx.x, lane = t & 31, w = t >> 5;
    int rbase = blockIdx.x * CLM;

    // stage A tile: 128 rows x 112 halves (smem stride BROW halves)
    const __nv_bfloat16* Ag = g_bf16 + (size_t)rbase * KPAD;
    for (int idx = t; idx < CLM*14; idx += 256) {
        int r = idx / 14, c = idx - r*14;
        *(uint4*)(smraw + (r*BROW + c*8)*2) = *(const uint4*)(Ag + r*KPAD + c*8);
    }
    __syncthreads();

    // A fragments for this warp's 16 rows: 7 k-chunks, ldmatrix.x4 each
    uint32_t Af[KC][4];
    {
        uint32_t aaddr = sbase + ((unsigned)(w*16 + (lane & 15))*BROW + ((lane >> 4)*8)) * 2;
        #pragma unroll
        for (int kc = 0; kc < KC; ++kc) {
            asm volatile("ldmatrix.sync.aligned.m8n8.x4.shared.b16 {%0,%1,%2,%3}, [%4];"
                : "=r"(Af[kc][0]), "=r"(Af[kc][1]), "=r"(Af[kc][2]), "=r"(Af[kc][3])
                : "r"(aaddr + kc*32));
        }
    }
    __syncthreads();

    // prologue: async-load B tile 0 into buffer 0
    {
        const __nv_bfloat16* Bg = g_bf16;
        for (int idx = t; idx < CLN*14; idx += 256) {
            int r = idx / 14, c = idx - r*14;
            uint32_t d = sbase + (unsigned)(r*BROW + c*8)*2;
            const void* s = Bg + r*KPAD + c*8;
            asm volatile("cp.async.cg.shared.global [%0], [%1], 16;" :: "r"(d), "l"(s));
        }
        asm volatile("cp.async.commit_group;" ::: "memory");
    }

    float tk0[TOPK], tk1[TOPK];
    #pragma unroll
    for (int i = 0; i < TOPK; ++i) { tk0[i] = -INFINITY; tk1[i] = -INFINITY; }

    int quad = lane >> 3, r8 = lane & 7;
    uint32_t bth = ((unsigned)(r8 + 8*(quad >> 1))*BROW + (quad & 1)*8) * 2;

    for (int tile = 0; tile < NTILES; ++tile) {
        asm volatile("cp.async.wait_group 0;" ::: "memory");
        __syncthreads();
        if (tile + 1 < NTILES) {
            const __nv_bfloat16* Bg = g_bf16 + (size_t)(tile + 1) * CLN * KPAD;
            uint32_t dst = sbase + (unsigned)((tile + 1) & 1) * (CLN*BROW*2);
            for (int idx = t; idx < CLN*14; idx += 256) {
                int r = idx / 14, c = idx - r*14;
                uint32_t d = dst + (unsigned)(r*BROW + c*8)*2;
                const void* s = Bg + r*KPAD + c*8;
                asm volatile("cp.async.cg.shared.global [%0], [%1], 16;" :: "r"(d), "l"(s));
            }
            asm volatile("cp.async.commit_group;" ::: "memory");
        }
        uint32_t bb = sbase + (unsigned)(tile & 1)*(CLN*BROW*2) + bth;
        int npairs = (tile == NTILES-1) ? 2 : 4;   // last tile: only cols 19968..19999
        for (int p = 0; p < npairs; ++p) {
            float d0[4] = {0.f,0.f,0.f,0.f}, d1[4] = {0.f,0.f,0.f,0.f};
            uint32_t ba = bb + (unsigned)p*(16*BROW*2);
            #pragma unroll
            for (int kc = 0; kc < KC; ++kc) {
                uint32_t b0, b1, b2, b3;
                asm volatile("ldmatrix.sync.aligned.m8n8.x4.shared.b16 {%0,%1,%2,%3}, [%4];"
                    : "=r"(b0), "=r"(b1), "=r"(b2), "=r"(b3) : "r"(ba + kc*32));
                asm volatile("mma.sync.aligned.m16n8k16.row.col.f32.bf16.bf16.f32 "
                    "{%0,%1,%2,%3}, {%4,%5,%6,%7}, {%8,%9}, {%0,%1,%2,%3};"
                    : "+f"(d0[0]), "+f"(d0[1]), "+f"(d0[2]), "+f"(d0[3])
                    : "r"(Af[kc][0]), "r"(Af[kc][1]), "r"(Af[kc][2]), "r"(Af[kc][3]),
                      "r"(b0), "r"(b1));
                asm volatile("mma.sync.aligned.m16n8k16.row.col.f32.bf16.bf16.f32 "
                    "{%0,%1,%2,%3}, {%4,%5,%6,%7}, {%8,%9}, {%0,%1,%2,%3};"
                    : "+f"(d1[0]), "+f"(d1[1]), "+f"(d1[2]), "+f"(d1[3])
                    : "r"(Af[kc][0]), "r"(Af[kc][1]), "r"(Af[kc][2]), "r"(Af[kc][3]),
                      "r"(b2), "r"(b3));
            }
            topk_insert(tk0, d0[0]*INV_TEMP); topk_insert(tk0, d0[1]*INV_TEMP);
            topk_insert(tk1, d0[2]*INV_TEMP); topk_insert(tk1, d0[3]*INV_TEMP);
            topk_insert(tk0, d1[0]*INV_TEMP); topk_insert(tk0, d1[1]*INV_TEMP);
            topk_insert(tk1, d1[2]*INV_TEMP); topk_insert(tk1, d1[3]*INV_TEMP);
        }
    }

    // merge: 4 threads (lane&3) per row, each thread holds rows g and g+8 of its warp strip
    __syncthreads();
    float* mg = (float*)smraw;                 // [128][40]
    int g = lane >> 2, i4 = lane & 3;
    int r0 = w*16 + g;
    #pragma unroll
    for (int q = 0; q < TOPK; ++q) {
        mg[r0*40 + i4*TOPK + q]     = tk0[q];
        mg[(r0+8)*40 + i4*TOPK + q] = tk1[q];
    }
    __syncthreads();
    if (t < CLM) {
        int row = rbase + t;
        if (row < N_NODE) {
            float m[TOPK];
            #pragma unroll
            for (int q = 0; q < TOPK; ++q) m[q] = -INFINITY;
            for (int q = 0; q < 4*TOPK; ++q) topk_insert(m, mg[t*40 + q]);
            float se = 0.0f;
            #pragma unroll
            for (int q = 1; q < TOPK; ++q) se += expf(m[q] - m[0]);
            atomicAdd(out_cl, log1pf(se) * (CL_WF / (float)N_NODE));
        }
    }
}

// ---------------- launch ----------------
extern "C" void kernel_launch(void* const* d_in, const int* in_sizes, int n_in,
                              void* d_out, int out_size) {
    const float* slen  = (const float*)d_in[1];
    const int*   rev   = (const int*)d_in[2];
    const int*   mask  = (const int*)d_in[3];
    const int*   tar   = (const int*)d_in[5];
    const int*   arow  = (const int*)d_in[8];
    const int*   acol  = (const int*)d_in[9];
    const float* avals = (const float*)d_in[10];
    const float* emb   = (const float*)d_in[11];
    const float* pos   = (const float*)d_in[12];
    const float* witem = (const float*)d_in[13];
    const float* attw  = (const float*)d_in[14];
    const float* attb  = (const float*)d_in[15];
    const float* w1    = (const float*)d_in[16];
    const float* w2    = (const float*)d_in[17];
    const float* glu1  = (const float*)d_in[18];
    const float* glu1b = (const float*)d_in[19];
    const float* glu2  = (const float*)d_in[20];
    float* out = (float*)d_out;
    int E = in_sizes[8];

    k_init<<<2048, 256>>>(emb, out, out_size);
    k_transpose<<<(N_LAYERS*EMB*EMB + 255)/256, 256>>>(witem, glu1, glu2);
    k_posw<<<SEQ, 128>>>(pos, w1);
    k_colsum<<<(E + 255)/256, 256>>>(acol, avals, E);

    for (int l = 0; l < N_LAYERS; ++l) {
        k_att_score<<<(N_NODE*32 + 255)/256, 256>>>(attw, attb);
        k_softmax_reduce<<<1, 1024>>>();
        k_lin_att<<<(N_NODE + 63)/64, 256>>>(l);
        k_spmm<<<(E*32 + 255)/256, 256>>>(arow, acol, avals, E);
        k_norm_acc<<<(N_NODE*32 + 255)/256, 256>>>();
    }

    k_item<<<(N_NODE*32 + 255)/256, 256>>>();
    k_bf16cvt<<<(ROWS_PAD*KPAD + 255)/256, 256>>>();
    k_sess<<<BATCH, 128>>>(rev, slen, mask, w1, w2, glu1b);
    k_sess_norm<<<(BATCH*32 + 255)/256, 256>>>();

    dim3 sg(N_NODE/32, BATCH/64);
    k_scores<<<sg, 256>>>(out + 1);

    k_loss<<<BATCH, 256>>>(out + 1, tar, out);
    k_cl_tc<<<NBLK, 256>>>(out + out_size - 1);
}

// round 6
// speedup vs baseline: 3.1455x; 1.0945x over previous
#include <cuda_runtime.h>
#include <cuda_bf16.h>
#include <math.h>
#include <stdint.h>

#define N_NODE 20000
#define EMB 100
#define BATCH 512
#define SEQ 50
#define N_LAYERS 2
#define INV_TEMP 10.0f
#define W_KF 10.0f
#define TOPK 10
#define CL_WF 100.0f
#define EPSN 1e-12f
#define EMAX 345000

// tensor-core cl gemm tiling
#define CLM 128
#define CLN 64
#define KPAD 112
#define KC 7
#define NBLK 157                // ceil(20000/128)
#define ROWS_PAD (NBLK*CLM)     // 20096
#define NTILES 313              // ceil(20000/64)
#define BROW 120                // smem row stride in halves
#define NQ 4
#define NITEMS (NBLK*NQ)        // 628
#define CLGRID 296

// ---------------- scratch ----------------
__device__ float g_colsum[N_NODE];
__device__ int   g_cnt[N_NODE];
__device__ int   g_rowptr[N_NODE+1];
__device__ int   g_cursor[N_NODE];
__device__ int   g_ecol[EMAX];
__device__ float g_eval[EMAX];
__device__ int   g_work;
__device__ float g_x[N_NODE*EMB];
__device__ float g_y[N_NODE*EMB];
__device__ float g_final[N_NODE*EMB];
__device__ float g_item[N_NODE*EMB];
__device__ float g_itemn[N_NODE*EMB];
__device__ float g_s[N_NODE];
__device__ float g_amax;
__device__ float g_asum;
__device__ float g_wT[N_LAYERS*EMB*EMB];
__device__ float g_glu1T[EMB*EMB];
__device__ float g_glu2T[EMB*EMB];
__device__ float g_sess[BATCH*EMB];
__device__ float g_sessn[BATCH*EMB];
__device__ float g_posw[SEQ*EMB];
__device__ float g_qtk[ROWS_PAD*NQ*TOPK];
__device__ __align__(16) __nv_bfloat16 g_bf16[ROWS_PAD*KPAD];

// ---------------- helpers ----------------
__device__ __forceinline__ float warp_sum(float v) {
    #pragma unroll
    for (int o = 16; o > 0; o >>= 1) v += __shfl_xor_sync(0xffffffffu, v, o);
    return v;
}

__device__ __forceinline__ void topk_insert(float (&tk)[TOPK], float v) {
    if (v > tk[TOPK-1]) {
        tk[TOPK-1] = v;
        #pragma unroll
        for (int i = TOPK-1; i > 0; --i) {
            if (tk[i] > tk[i-1]) { float tmp = tk[i-1]; tk[i-1] = tk[i]; tk[i] = tmp; }
        }
    }
}

// ---------------- init ----------------
__global__ void k_init(const float* __restrict__ emb, float* __restrict__ out, int out_size) {
    int stride = gridDim.x * blockDim.x;
    int i0 = blockIdx.x * blockDim.x + threadIdx.x;
    for (int i = i0; i < N_NODE*EMB; i += stride) {
        float v = emb[i];
        g_x[i] = v;
        g_final[i] = v;
        if (i < N_NODE) { g_colsum[i] = 0.0f; g_cnt[i] = 0; }
    }
    if (i0 == 0) { out[0] = 0.0f; out[out_size-1] = 0.0f; g_work = 0; }
}

// ---------------- transpose weights ----------------
__global__ void k_transpose(const float* __restrict__ w_item,
                            const float* __restrict__ glu1,
                            const float* __restrict__ glu2) {
    int i = blockIdx.x * blockDim.x + threadIdx.x;
    if (i < N_LAYERS*EMB*EMB) {
        int l = i / (EMB*EMB);
        int r = i - l*(EMB*EMB);
        int j = r / EMB, k = r - j*EMB;
        g_wT[l*EMB*EMB + j*EMB + k] = w_item[l*EMB*EMB + k*EMB + j];
    }
    if (i < EMB*EMB) {
        int j = i / EMB, k = i - j*EMB;
        g_glu1T[j*EMB + k] = glu1[k*EMB + j];
        g_glu2T[j*EMB + k] = glu2[k*EMB + j];
    }
}

// ---------------- posW[l][t] ----------------
__global__ void k_posw(const float* __restrict__ pos, const float* __restrict__ w1) {
    int l = blockIdx.x, t = threadIdx.x;
    if (t < EMB) {
        float acc = 0.0f;
        for (int j = 0; j < EMB; ++j) acc += pos[l*EMB + j] * w1[j*EMB + t];
        g_posw[l*EMB + t] = acc;
    }
}

// ---------------- one edge pass: column sums + row degree counts ----------------
__global__ void k_prep(const int* __restrict__ row, const int* __restrict__ col,
                       const float* __restrict__ vals, int E) {
    int e = blockIdx.x * blockDim.x + threadIdx.x;
    if (e < E) {
        atomicAdd(&g_colsum[col[e]], vals[e]);
        atomicAdd(&g_cnt[row[e]], 1);
    }
}

// ---------------- exclusive prefix sum of degree counts -> rowptr, cursor ----------------
__global__ void k_scan() {
    __shared__ int sh[1024];
    int t = threadIdx.x;
    const int CH = 20;          // 1024*20 = 20480 >= 20000
    int local[CH];
    int s = 0;
    #pragma unroll
    for (int i = 0; i < CH; ++i) {
        int idx = t*CH + i;
        int c = (idx < N_NODE) ? g_cnt[idx] : 0;
        local[i] = s; s += c;
    }
    sh[t] = s; __syncthreads();
    for (int off = 1; off < 1024; off <<= 1) {
        int v = (t >= off) ? sh[t-off] : 0;
        __syncthreads();
        if (t >= off) sh[t] += v;
        __syncthreads();
    }
    int base = (t == 0) ? 0 : sh[t-1];
    #pragma unroll
    for (int i = 0; i < CH; ++i) {
        int idx = t*CH + i;
        if (idx < N_NODE) {
            int p = base + local[i];
            g_rowptr[idx] = p;
            g_cursor[idx] = p;
        }
    }
    if (t == 1023) g_rowptr[N_NODE] = sh[1023];
}

// ---------------- scatter edges into CSR with normalized values ----------------
__global__ void k_scatter(const int* __restrict__ row, const int* __restrict__ col,
                          const float* __restrict__ vals, int E) {
    int e = blockIdx.x * blockDim.x + threadIdx.x;
    if (e >= E) return;
    int c = col[e], r = row[e];
    float v = vals[e] / g_colsum[c];
    int p = atomicAdd(&g_cursor[r], 1);
    g_ecol[p] = c;
    g_eval[p] = v;
}

// ---------------- attention scores ----------------
__global__ void k_att_score(const float* __restrict__ attw, const float* __restrict__ attb) {
    int gw = (blockIdx.x * blockDim.x + threadIdx.x) >> 5;
    int lane = threadIdx.x & 31;
    if (gw >= N_NODE) return;
    const float* xr = g_x + gw*EMB;
    float acc = 0.0f;
    for (int k = lane; k < EMB; k += 32) acc += xr[k] * attw[k];
    acc = warp_sum(acc);
    if (lane == 0) g_s[gw] = acc + attb[0];
}

// ---------------- softmax reduce ----------------
__global__ void k_softmax_reduce() {
    __shared__ float sh[1024];
    int t = threadIdx.x;
    float m = -INFINITY;
    for (int i = t; i < N_NODE; i += 1024) m = fmaxf(m, g_s[i]);
    sh[t] = m; __syncthreads();
    for (int s = 512; s > 0; s >>= 1) { if (t < s) sh[t] = fmaxf(sh[t], sh[t+s]); __syncthreads(); }
    float mx = sh[0]; __syncthreads();
    float sum = 0.0f;
    for (int i = t; i < N_NODE; i += 1024) sum += expf(g_s[i] - mx);
    sh[t] = sum; __syncthreads();
    for (int s = 512; s > 0; s >>= 1) { if (t < s) sh[t] += sh[t+s]; __syncthreads(); }
    if (t == 0) { g_amax = mx; g_asum = sh[0]; }
}

// ---------------- y = (x @ W^T) * att ----------------
__global__ void k_lin_att(int layer) {
    __shared__ float xs[64*EMB];
    int base = blockIdx.x * 64;
    int t = threadIdx.x;
    int nvalid = min(64, N_NODE - base);
    for (int idx = t; idx < nvalid*EMB; idx += 256) xs[idx] = g_x[base*EMB + idx];
    __syncthreads();
    const float* WT = g_wT + layer*EMB*EMB;
    float inv = 1.0f / g_asum;
    float mx  = g_amax;
    for (int o = t; o < nvalid*EMB; o += 256) {
        int n = o / EMB, k = o - n*EMB;
        float acc = 0.0f;
        #pragma unroll 4
        for (int j = 0; j < EMB; ++j) acc += xs[n*EMB + j] * WT[j*EMB + k];
        float att = expf(g_s[base + n] - mx) * inv;
        g_y[base*EMB + o] = acc * att;
    }
}

// ---------------- CSR SpMM fused with l2norm + final accumulate (warp per row) ----------------
__global__ void k_spmm_csr() {
    int gw = (blockIdx.x * blockDim.x + threadIdx.x) >> 5;
    int lane = threadIdx.x & 31;
    if (gw >= N_NODE) return;
    int s = g_rowptr[gw], e = g_rowptr[gw+1];
    bool act = lane < 25;       // 25 lanes x float4 = 100 floats
    float4 acc = make_float4(0.f, 0.f, 0.f, 0.f);
    for (int i = s; i < e; ++i) {
        int c = g_ecol[i];        // broadcast load
        float v = g_eval[i];
        if (act) {
            float4 yv = *(const float4*)(g_y + (size_t)c*EMB + lane*4);
            acc.x += v*yv.x; acc.y += v*yv.y; acc.z += v*yv.z; acc.w += v*yv.w;
        }
    }
    float ss = acc.x*acc.x + acc.y*acc.y + acc.z*acc.z + acc.w*acc.w;
    ss = warp_sum(ss);
    float invn = 1.0f / fmaxf(sqrtf(ss), EPSN);
    if (act) {
        float4 nv = make_float4(acc.x*invn, acc.y*invn, acc.z*invn, acc.w*invn);
        *(float4*)(g_x + (size_t)gw*EMB + lane*4) = nv;
        float4 f = *(const float4*)(g_final + (size_t)gw*EMB + lane*4);
        f.x += nv.x; f.y += nv.y; f.z += nv.z; f.w += nv.w;
        *(float4*)(g_final + (size_t)gw*EMB + lane*4) = f;
    }
}

// ---------------- item_emb = final/3 ; item_n = l2norm ; bf16 fused ----------------
__global__ void k_item() {
    int gw = (blockIdx.x * blockDim.x + threadIdx.x) >> 5;
    int lane = threadIdx.x & 31;
    if (gw >= N_NODE) return;
    const float inv3 = 1.0f / 3.0f;
    float ss = 0.0f;
    float v[4];
    #pragma unroll
    for (int i = 0; i < 4; ++i) {
        int k = lane + 32*i;
        v[i] = (k < EMB) ? g_final[gw*EMB + k] * inv3 : 0.0f;
        ss += v[i]*v[i];
    }
    ss = warp_sum(ss);
    float invn = 1.0f / fmaxf(sqrtf(ss), EPSN);
    #pragma unroll
    for (int i = 0; i < 4; ++i) {
        int k = lane + 32*i;
        if (k < EMB) {
            float nv = v[i] * invn;
            g_item[gw*EMB + k]  = v[i];
            g_itemn[gw*EMB + k] = nv;
            g_bf16[(size_t)gw*KPAD + k] = __float2bfloat16(nv);
        }
    }
    if (lane < KPAD - EMB) g_bf16[(size_t)gw*KPAD + EMB + lane] = __float2bfloat16(0.0f);
}

// ---------------- session embedding ----------------
__global__ void k_sess(const int* __restrict__ rev, const float* __restrict__ slen,
                       const int* __restrict__ mask, const float* __restrict__ w1,
                       const float* __restrict__ w2, const float* __restrict__ glu1b) {
    __shared__ float sh_seq[SEQ*EMB];
    __shared__ float sh_hs[EMB];
    __shared__ float sh_hsg[EMB];
    __shared__ float sh_nh[EMB];
    __shared__ float sh_red[128];
    int b = blockIdx.x, t = threadIdx.x;

    for (int idx = t; idx < SEQ*EMB; idx += 128) {
        int l = idx / EMB, k = idx - l*EMB;
        int id = rev[b*SEQ + l];
        sh_seq[idx] = (id == 0) ? 0.0f : g_item[(size_t)(id-1)*EMB + k];
    }
    __syncthreads();
    if (t < EMB) {
        float acc = 0.0f;
        for (int l = 0; l < SEQ; ++l) acc += sh_seq[l*EMB + t];
        sh_hs[t] = acc / slen[b];
    }
    __syncthreads();
    if (t < EMB) {
        float acc = 0.0f;
        for (int j = 0; j < EMB; ++j) acc += sh_hs[j] * g_glu2T[j*EMB + t];
        sh_hsg[t] = acc;
    }
    __syncthreads();

    float sess_k = 0.0f;
    for (int l = 0; l < SEQ; ++l) {
        if (t < EMB) {
            float acc = g_posw[l*EMB + t];
            for (int j = 0; j < EMB; ++j) acc += sh_seq[l*EMB + j] * w1[(EMB+j)*EMB + t];
            sh_nh[t] = tanhf(acc);
        }
        __syncthreads();
        float prod = 0.0f;
        if (t < EMB) {
            float acc = sh_hsg[t] + glu1b[t];
            for (int j = 0; j < EMB; ++j) acc += sh_nh[j] * g_glu1T[j*EMB + t];
            float g = 1.0f / (1.0f + expf(-acc));
            prod = g * w2[t];
        }
        sh_red[t] = prod;
        __syncthreads();
        for (int s = 64; s > 0; s >>= 1) {
            if (t < s) sh_red[t] += sh_red[t+s];
            __syncthreads();
        }
        float beta = sh_red[0] * (float)mask[b*SEQ + l];
        if (t < EMB) sess_k += beta * sh_seq[l*EMB + t];
        __syncthreads();
    }
    if (t < EMB) g_sess[b*EMB + t] = sess_k;
}

// ---------------- sess = W_K * l2norm(sess) ----------------
__global__ void k_sess_norm() {
    int gw = (blockIdx.x * blockDim.x + threadIdx.x) >> 5;
    int lane = threadIdx.x & 31;
    if (gw >= BATCH) return;
    float ss = 0.0f;
    float v[4];
    #pragma unroll
    for (int i = 0; i < 4; ++i) {
        int k = lane + 32*i;
        v[i] = (k < EMB) ? g_sess[gw*EMB + k] : 0.0f;
        ss += v[i]*v[i];
    }
    ss = warp_sum(ss);
    float sc = W_KF / fmaxf(sqrtf(ss), EPSN);
    #pragma unroll
    for (int i = 0; i < 4; ++i) {
        int k = lane + 32*i;
        if (k < EMB) g_sessn[gw*EMB + k] = v[i] * sc;
    }
}

// ---------------- scores = sessn @ itemn^T ----------------
#define ITS_STRIDE 104
__global__ void k_scores(float* __restrict__ scores) {
    __shared__ __align__(16) float its[32*ITS_STRIDE];
    __shared__ __align__(16) float ses[64*EMB];
    int t = threadIdx.x;
    int nb = blockIdx.x * 32;
    int bb = blockIdx.y * 64;
    for (int i = t; i < 32*EMB; i += 256) {
        int r = i / EMB, k = i - r*EMB;
        its[r*ITS_STRIDE + k] = g_itemn[(size_t)nb*EMB + i];
    }
    for (int i = t; i < 64*EMB; i += 256) ses[i] = g_sessn[(size_t)bb*EMB + i];
    __syncthreads();
    int c = t & 31;
    int g = t >> 5;
    float acc[8];
    #pragma unroll
    for (int i = 0; i < 8; ++i) acc[i] = 0.0f;
    #pragma unroll 5
    for (int k4 = 0; k4 < EMB/4; ++k4) {
        float4 iv = *(const float4*)&its[c*ITS_STRIDE + k4*4];
        #pragma unroll
        for (int i = 0; i < 8; ++i) {
            float4 sv = *(const float4*)&ses[(g*8 + i)*EMB + k4*4];
            acc[i] += iv.x*sv.x + iv.y*sv.y + iv.z*sv.z + iv.w*sv.w;
        }
    }
    #pragma unroll
    for (int i = 0; i < 8; ++i) {
        int b = bb + g*8 + i;
        scores[(size_t)b * N_NODE + nb + c] = acc[i];
    }
}

// ---------------- loss_item: single-pass online CE ----------------
__global__ void k_loss(const float* __restrict__ scores, const int* __restrict__ tar,
                       float* __restrict__ out0) {
    __shared__ float shm[256], shs[256];
    int b = blockIdx.x, t = threadIdx.x;
    const float* row = scores + (size_t)b * N_NODE;
    float m = -INFINITY, s = 0.0f;
    for (int i = t; i < N_NODE; i += 256) {
        float v = row[i];
        if (v > m) { s = s * expf(m - v) + 1.0f; m = v; }
        else       { s += expf(v - m); }
    }
    shm[t] = m; shs[t] = s; __syncthreads();
    for (int o = 128; o > 0; o >>= 1) {
        if (t < o) {
            float m2 = shm[t+o], s2 = shs[t+o];
            float M = fmaxf(shm[t], m2);
            shs[t] = shs[t]*expf(shm[t]-M) + s2*expf(m2-M);
            shm[t] = M;
        }
        __syncthreads();
    }
    if (t == 0) {
        float lse = shm[0] + logf(shs[0]);
        atomicAdd(out0, (lse - row[tar[b]]) * (1.0f / BATCH));
    }
}

// ---------------- cl GEMM: persistent work-queue over (rowblock, N-quarter) ----------------
__global__ __launch_bounds__(256, 2) void k_cl_tc() {
    __shared__ __align__(16) char smraw[2*CLN*BROW*2];
    __shared__ int sh_item;
    uint32_t sbase = (uint32_t)__cvta_generic_to_shared(smraw);
    int t = threadIdx.x, lane = t & 31, w = t >> 5;

    for (;;) {
        __syncthreads();
        if (t == 0) sh_item = atomicAdd(&g_work, 1);
        __syncthreads();
        int item = sh_item;
        if (item >= NITEMS) return;
        int rowblk = item >> 2, q = item & 3;
        int rbase = rowblk * CLM;
        int qs = (q * NTILES) / 4, qe = ((q+1) * NTILES) / 4;

        // stage A tile
        const __nv_bfloat16* Ag = g_bf16 + (size_t)rbase * KPAD;
        for (int idx = t; idx < CLM*14; idx += 256) {
            int r = idx / 14, c = idx - r*14;
            *(uint4*)(smraw + (r*BROW + c*8)*2) = *(const uint4*)(Ag + r*KPAD + c*8);
        }
        __syncthreads();

        uint32_t Af[KC][4];
        {
            uint32_t aaddr = sbase + ((unsigned)(w*16 + (lane & 15))*BROW + ((lane >> 4)*8)) * 2;
            #pragma unroll
            for (int kc = 0; kc < KC; ++kc) {
                asm volatile("ldmatrix.sync.aligned.m8n8.x4.shared.b16 {%0,%1,%2,%3}, [%4];"
                    : "=r"(Af[kc][0]), "=r"(Af[kc][1]), "=r"(Af[kc][2]), "=r"(Af[kc][3])
                    : "r"(aaddr + kc*32));
            }
        }
        __syncthreads();

        // prologue: async-load first B tile
        {
            const __nv_bfloat16* Bg = g_bf16 + (size_t)qs * CLN * KPAD;
            uint32_t dst = sbase + (unsigned)(qs & 1) * (CLN*BROW*2);
            for (int idx = t; idx < CLN*14; idx += 256) {
                int r = idx / 14, c = idx - r*14;
                uint32_t d = dst + (unsigned)(r*BROW + c*8)*2;
                const void* s = Bg + r*KPAD + c*8;
                asm volatile("cp.async.cg.shared.global [%0], [%1], 16;" :: "r"(d), "l"(s));
            }
            asm volatile("cp.async.commit_group;" ::: "memory");
        }

        float tk0[TOPK], tk1[TOPK];
        #pragma unroll
        for (int i = 0; i < TOPK; ++i) { tk0[i] = -INFINITY; tk1[i] = -INFINITY; }

        int quad = lane >> 3, r8 = lane & 7;
        uint32_t bth = ((unsigned)(r8 + 8*(quad >> 1))*BROW + (quad & 1)*8) * 2;

        for (int tile = qs; tile < qe; ++tile) {
            asm volatile("cp.async.wait_group 0;" ::: "memory");
            __syncthreads();
            if (tile + 1 < qe) {
                const __nv_bfloat16* Bg = g_bf16 + (size_t)(tile + 1) * CLN * KPAD;
                uint32_t dst = sbase + (unsigned)((tile + 1) & 1) * (CLN*BROW*2);
                for (int idx = t; idx < CLN*14; idx += 256) {
                    int r = idx / 14, c = idx - r*14;
                    uint32_t d = dst + (unsigned)(r*BROW + c*8)*2;
                    const void* s = Bg + r*KPAD + c*8;
                    asm volatile("cp.async.cg.shared.global [%0], [%1], 16;" :: "r"(d), "l"(s));
                }
                asm volatile("cp.async.commit_group;" ::: "memory");
            }
            uint32_t bb = sbase + (unsigned)(tile & 1)*(CLN*BROW*2) + bth;
            int npairs = (tile == NTILES-1) ? 2 : 4;
            for (int p = 0; p < npairs; ++p) {
                float d0[4] = {0.f,0.f,0.f,0.f}, d1[4] = {0.f,0.f,0.f,0.f};
                uint32_t ba = bb + (unsigned)p*(16*BROW*2);
                #pragma unroll
                for (int kc = 0; kc < KC; ++kc) {
                    uint32_t b0, b1, b2, b3;
                    asm volatile("ldmatrix.sync.aligned.m8n8.x4.shared.b16 {%0,%1,%2,%3}, [%4];"
                        : "=r"(b0), "=r"(b1), "=r"(b2), "=r"(b3) : "r"(ba + kc*32));
                    asm volatile("mma.sync.aligned.m16n8k16.row.col.f32.bf16.bf16.f32 "
                        "{%0,%1,%2,%3}, {%4,%5,%6,%7}, {%8,%9}, {%0,%1,%2,%3};"
                        : "+f"(d0[0]), "+f"(d0[1]), "+f"(d0[2]), "+f"(d0[3])
                        : "r"(Af[kc][0]), "r"(Af[kc][1]), "r"(Af[kc][2]), "r"(Af[kc][3]),
                          "r"(b0), "r"(b1));
                    asm volatile("mma.sync.aligned.m16n8k16.row.col.f32.bf16.bf16.f32 "
                        "{%0,%1,%2,%3}, {%4,%5,%6,%7}, {%8,%9}, {%0,%1,%2,%3};"
                        : "+f"(d1[0]), "+f"(d1[1]), "+f"(d1[2]), "+f"(d1[3])
                        : "r"(Af[kc][0]), "r"(Af[kc][1]), "r"(Af[kc][2]), "r"(Af[kc][3]),
                          "r"(b2), "r"(b3));
                }
                topk_insert(tk0, d0[0]*INV_TEMP); topk_insert(tk0, d0[1]*INV_TEMP);
                topk_insert(tk1, d0[2]*INV_TEMP); topk_insert(tk1, d0[3]*INV_TEMP);
                topk_insert(tk0, d1[0]*INV_TEMP); topk_insert(tk0, d1[1]*INV_TEMP);
                topk_insert(tk1, d1[2]*INV_TEMP); topk_insert(tk1, d1[3]*INV_TEMP);
            }
        }

        // merge 4 thread-local lists per row -> per-quarter top-10 in global buffer
        __syncthreads();
        float* mg = (float*)smraw;              // [128][40]
        int g = lane >> 2, i4 = lane & 3;
        int r0 = w*16 + g;
        #pragma unroll
        for (int qq = 0; qq < TOPK; ++qq) {
            mg[r0*40 + i4*TOPK + qq]     = tk0[qq];
            mg[(r0+8)*40 + i4*TOPK + qq] = tk1[qq];
        }
        __syncthreads();
        if (t < CLM) {
            int row = rbase + t;
            if (row < N_NODE) {
                float m[TOPK];
                #pragma unroll
                for (int qq = 0; qq < TOPK; ++qq) m[qq] = -INFINITY;
                for (int qq = 0; qq < 4*TOPK; ++qq) topk_insert(m, mg[t*40 + qq]);
                #pragma unroll
                for (int qq = 0; qq < TOPK; ++qq)
                    g_qtk[((size_t)row*NQ + q)*TOPK + qq] = m[qq];
            }
        }
    }
}

// ---------------- cl merge: combine 4 quarter top-10s per row, block-reduced atomics ----------------
__global__ void k_cl_merge(float* __restrict__ out_cl) {
    __shared__ float sh[256];
    int idx = blockIdx.x * 256 + threadIdx.x;
    float contrib = 0.0f;
    if (idx < N_NODE) {
        float m[TOPK];
        #pragma unroll
        for (int q = 0; q < TOPK; ++q) m[q] = -INFINITY;
        const float* p = g_qtk + (size_t)idx*NQ*TOPK;
        for (int q = 0; q < NQ*TOPK; ++q) topk_insert(m, p[q]);
        float se = 0.0f;
        #pragma unroll
        for (int q = 1; q < TOPK; ++q) se += expf(m[q] - m[0]);
        contrib = log1pf(se) * (CL_WF / (float)N_NODE);
    }
    sh[threadIdx.x] = contrib; __syncthreads();
    for (int s = 128; s > 0; s >>= 1) {
        if (threadIdx.x < s) sh[threadIdx.x] += sh[threadIdx.x + s];
        __syncthreads();
    }
    if (threadIdx.x == 0) atomicAdd(out_cl, sh[0]);
}

// ---------------- launch ----------------
extern "C" void kernel_launch(void* const* d_in, const int* in_sizes, int n_in,
                              void* d_out, int out_size) {
    const float* slen  = (const float*)d_in[1];
    const int*   rev   = (const int*)d_in[2];
    const int*   mask  = (const int*)d_in[3];
    const int*   tar   = (const int*)d_in[5];
    const int*   arow  = (const int*)d_in[8];
    const int*   acol  = (const int*)d_in[9];
    const float* avals = (const float*)d_in[10];
    const float* emb   = (const float*)d_in[11];
    const float* pos   = (const float*)d_in[12];
    const float* witem = (const float*)d_in[13];
    const float* attw  = (const float*)d_in[14];
    const float* attb  = (const float*)d_in[15];
    const float* w1    = (const float*)d_in[16];
    const float* w2    = (const float*)d_in[17];
    const float* glu1  = (const float*)d_in[18];
    const float* glu1b = (const float*)d_in[19];
    const float* glu2  = (const float*)d_in[20];
    float* out = (float*)d_out;
    int E = in_sizes[8];

    k_init<<<2048, 256>>>(emb, out, out_size);
    k_transpose<<<(N_LAYERS*EMB*EMB + 255)/256, 256>>>(witem, glu1, glu2);
    k_posw<<<SEQ, 128>>>(pos, w1);
    k_prep<<<(E + 255)/256, 256>>>(arow, acol, avals, E);
    k_scan<<<1, 1024>>>();
    k_scatter<<<(E + 255)/256, 256>>>(arow, acol, avals, E);

    for (int l = 0; l < N_LAYERS; ++l) {
        k_att_score<<<(N_NODE*32 + 255)/256, 256>>>(attw, attb);
        k_softmax_reduce<<<1, 1024>>>();
        k_lin_att<<<(N_NODE + 63)/64, 256>>>(l);
        k_spmm_csr<<<(N_NODE*32 + 255)/256, 256>>>();
    }

    k_item<<<(N_NODE*32 + 255)/256, 256>>>();
    k_sess<<<BATCH, 128>>>(rev, slen, mask, w1, w2, glu1b);
    k_sess_norm<<<(BATCH*32 + 255)/256, 256>>>();

    dim3 sg(N_NODE/32, BATCH/64);
    k_scores<<<sg, 256>>>(out + 1);

    k_loss<<<BATCH, 256>>>(out + 1, tar, out);
    k_cl_tc<<<CLGRID, 256>>>();
    k_cl_merge<<<(N_NODE + 255)/256, 256>>>(out + out_size - 1);
}

// round 8
// speedup vs baseline: 3.1561x; 1.0034x over previous
#include <cuda_runtime.h>
#include <cuda_bf16.h>
#include <math.h>
#include <stdint.h>

#define N_NODE 20000
#define EMB 100
#define BATCH 512
#define SEQ 50
#define N_LAYERS 2
#define INV_TEMP 10.0f
#define W_KF 10.0f
#define TOPK 10
#define CL_WF 100.0f
#define EPSN 1e-12f
#define EMAX 345000

// mma.sync cl gemm tiling
#define KPAD 112                // K padded to 7*16
#define KC 7
#define CLM 128                 // rows per CTA
#define CLN 64                  // cols per tile
#define NBLK 157                // ceil(20000/128)
#define ROWS_PAD (NBLK*CLM)     // 20096
#define NTILES 313              // ceil(20000/64)
#define BROW 120                // smem row stride in halves (240B)
#define NQ 8
#define NITEMS (NBLK*NQ)        // 1256
#define CLGRID 296
#define A_BYTES (CLM*BROW*2)    // 30720
#define B_BYTES (CLN*BROW*2)    // 15360
#define CL_SMEM (A_BYTES + 2*B_BYTES)  // 61440

// ---------------- scratch ----------------
__device__ float g_colsum[N_NODE];
__device__ int   g_cnt[N_NODE];
__device__ int   g_rowptr[N_NODE+1];
__device__ int   g_cursor[N_NODE];
__device__ int   g_ecol[EMAX];
__device__ float g_eval[EMAX];
__device__ int   g_work;
__device__ float g_x[N_NODE*EMB];
__device__ float g_y[N_NODE*EMB];
__device__ float g_final[N_NODE*EMB];
__device__ float g_item[N_NODE*EMB];
__device__ float g_itemn[N_NODE*EMB];
__device__ float g_s[N_NODE];
__device__ float g_amax;
__device__ float g_asum;
__device__ float g_wT[N_LAYERS*EMB*EMB];
__device__ float g_glu1T[EMB*EMB];
__device__ float g_glu2T[EMB*EMB];
__device__ float g_sess[BATCH*EMB];
__device__ float g_sessn[BATCH*EMB];
__device__ float g_posw[SEQ*EMB];
__device__ float g_qtk[(size_t)ROWS_PAD*NQ*TOPK];
__device__ __align__(16) __nv_bfloat16 g_bf16[(size_t)ROWS_PAD*KPAD];

// ---------------- helpers ----------------
__device__ __forceinline__ float warp_sum(float v) {
    #pragma unroll
    for (int o = 16; o > 0; o >>= 1) v += __shfl_xor_sync(0xffffffffu, v, o);
    return v;
}

__device__ __forceinline__ void topk_insert(float (&tk)[TOPK], float v) {
    if (v > tk[TOPK-1]) {
        tk[TOPK-1] = v;
        #pragma unroll
        for (int i = TOPK-1; i > 0; --i) {
            if (tk[i] > tk[i-1]) { float tmp = tk[i-1]; tk[i-1] = tk[i]; tk[i] = tmp; }
        }
    }
}

// ---------------- init ----------------
__global__ void k_init(const float* __restrict__ emb, float* __restrict__ out, int out_size) {
    int stride = gridDim.x * blockDim.x;
    int i0 = blockIdx.x * blockDim.x + threadIdx.x;
    for (int i = i0; i < N_NODE*EMB; i += stride) {
        float v = emb[i];
        g_x[i] = v;
        g_final[i] = v;
        if (i < N_NODE) { g_colsum[i] = 0.0f; g_cnt[i] = 0; }
    }
    for (int i = i0; i < (ROWS_PAD - N_NODE)*KPAD; i += stride)
        g_bf16[(size_t)N_NODE*KPAD + i] = __float2bfloat16(0.0f);
    if (i0 == 0) { out[0] = 0.0f; out[out_size-1] = 0.0f; g_work = 0; }
}

// ---------------- transpose weights ----------------
__global__ void k_transpose(const float* __restrict__ w_item,
                            const float* __restrict__ glu1,
                            const float* __restrict__ glu2) {
    int i = blockIdx.x * blockDim.x + threadIdx.x;
    if (i < N_LAYERS*EMB*EMB) {
        int l = i / (EMB*EMB);
        int r = i - l*(EMB*EMB);
        int j = r / EMB, k = r - j*EMB;
        g_wT[l*EMB*EMB + j*EMB + k] = w_item[l*EMB*EMB + k*EMB + j];
    }
    if (i < EMB*EMB) {
        int j = i / EMB, k = i - j*EMB;
        g_glu1T[j*EMB + k] = glu1[k*EMB + j];
        g_glu2T[j*EMB + k] = glu2[k*EMB + j];
    }
}

// ---------------- posW ----------------
__global__ void k_posw(const float* __restrict__ pos, const float* __restrict__ w1) {
    int l = blockIdx.x, t = threadIdx.x;
    if (t < EMB) {
        float acc = 0.0f;
        for (int j = 0; j < EMB; ++j) acc += pos[l*EMB + j] * w1[j*EMB + t];
        g_posw[l*EMB + t] = acc;
    }
}

// ---------------- edge pass: column sums + row degrees ----------------
__global__ void k_prep(const int* __restrict__ row, const int* __restrict__ col,
                       const float* __restrict__ vals, int E) {
    int e = blockIdx.x * blockDim.x + threadIdx.x;
    if (e < E) {
        atomicAdd(&g_colsum[col[e]], vals[e]);
        atomicAdd(&g_cnt[row[e]], 1);
    }
}

// ---------------- prefix sum -> rowptr ----------------
__global__ void k_scan() {
    __shared__ int sh[1024];
    int t = threadIdx.x;
    const int CH = 20;
    int local[CH];
    int s = 0;
    #pragma unroll
    for (int i = 0; i < CH; ++i) {
        int idx = t*CH + i;
        int c = (idx < N_NODE) ? g_cnt[idx] : 0;
        local[i] = s; s += c;
    }
    sh[t] = s; __syncthreads();
    for (int off = 1; off < 1024; off <<= 1) {
        int v = (t >= off) ? sh[t-off] : 0;
        __syncthreads();
        if (t >= off) sh[t] += v;
        __syncthreads();
    }
    int base = (t == 0) ? 0 : sh[t-1];
    #pragma unroll
    for (int i = 0; i < CH; ++i) {
        int idx = t*CH + i;
        if (idx < N_NODE) {
            int p = base + local[i];
            g_rowptr[idx] = p;
            g_cursor[idx] = p;
        }
    }
    if (t == 1023) g_rowptr[N_NODE] = sh[1023];
}

// ---------------- scatter edges into CSR ----------------
__global__ void k_scatter(const int* __restrict__ row, const int* __restrict__ col,
                          const float* __restrict__ vals, int E) {
    int e = blockIdx.x * blockDim.x + threadIdx.x;
    if (e >= E) return;
    int c = col[e], r = row[e];
    float v = vals[e] / g_colsum[c];
    int p = atomicAdd(&g_cursor[r], 1);
    g_ecol[p] = c;
    g_eval[p] = v;
}

// ---------------- attention scores ----------------
__global__ void k_att_score(const float* __restrict__ attw, const float* __restrict__ attb) {
    int gw = (blockIdx.x * blockDim.x + threadIdx.x) >> 5;
    int lane = threadIdx.x & 31;
    if (gw >= N_NODE) return;
    const float* xr = g_x + gw*EMB;
    float acc = 0.0f;
    for (int k = lane; k < EMB; k += 32) acc += xr[k] * attw[k];
    acc = warp_sum(acc);
    if (lane == 0) g_s[gw] = acc + attb[0];
}

// ---------------- softmax reduce ----------------
__global__ void k_softmax_reduce() {
    __shared__ float sh[1024];
    int t = threadIdx.x;
    float m = -INFINITY;
    for (int i = t; i < N_NODE; i += 1024) m = fmaxf(m, g_s[i]);
    sh[t] = m; __syncthreads();
    for (int s = 512; s > 0; s >>= 1) { if (t < s) sh[t] = fmaxf(sh[t], sh[t+s]); __syncthreads(); }
    float mx = sh[0]; __syncthreads();
    float sum = 0.0f;
    for (int i = t; i < N_NODE; i += 1024) sum += expf(g_s[i] - mx);
    sh[t] = sum; __syncthreads();
    for (int s = 512; s > 0; s >>= 1) { if (t < s) sh[t] += sh[t+s]; __syncthreads(); }
    if (t == 0) { g_amax = mx; g_asum = sh[0]; }
}

// ---------------- y = (x @ W^T) * att  (WT staged in smem) ----------------
__global__ void k_lin_att(int layer) {
    extern __shared__ float sm_la[];
    float* WT = sm_la;            // [100][100]
    float* xs = sm_la + EMB*EMB;  // [64][100]
    int base = blockIdx.x * 64;
    int t = threadIdx.x;
    int nvalid = min(64, N_NODE - base);
    const float* WTg = g_wT + layer*EMB*EMB;
    for (int i = t; i < EMB*EMB; i += 256) WT[i] = WTg[i];
    for (int i = t; i < nvalid*EMB; i += 256) xs[i] = g_x[base*EMB + i];
    __syncthreads();
    float inv = 1.0f / g_asum;
    float mx  = g_amax;
    int npairs = nvalid * 25;
    for (int p = t; p < npairs; p += 256) {
        int n = p / 25, k4 = p - n*25;
        float a0 = 0.f, a1 = 0.f, a2 = 0.f, a3 = 0.f;
        const float* xr = xs + n*EMB;
        #pragma unroll 4
        for (int j = 0; j < EMB; ++j) {
            float xv = xr[j];
            float4 wv = *(const float4*)&WT[j*EMB + k4*4];
            a0 += xv*wv.x; a1 += xv*wv.y; a2 += xv*wv.z; a3 += xv*wv.w;
        }
        float att = expf(g_s[base + n] - mx) * inv;
        float4 o = make_float4(a0*att, a1*att, a2*att, a3*att);
        *(float4*)(g_y + (size_t)(base + n)*EMB + k4*4) = o;
    }
}

// ---------------- CSR SpMM fused with l2norm + final accumulate ----------------
__global__ void k_spmm_csr() {
    int gw = (blockIdx.x * blockDim.x + threadIdx.x) >> 5;
    int lane = threadIdx.x & 31;
    if (gw >= N_NODE) return;
    int s = g_rowptr[gw], e = g_rowptr[gw+1];
    bool act = lane < 25;
    float4 acc = make_float4(0.f, 0.f, 0.f, 0.f);
    for (int i = s; i < e; ++i) {
        int c = g_ecol[i];
        float v = g_eval[i];
        if (act) {
            float4 yv = *(const float4*)(g_y + (size_t)c*EMB + lane*4);
            acc.x += v*yv.x; acc.y += v*yv.y; acc.z += v*yv.z; acc.w += v*yv.w;
        }
    }
    float ss = acc.x*acc.x + acc.y*acc.y + acc.z*acc.z + acc.w*acc.w;
    ss = warp_sum(ss);
    float invn = 1.0f / fmaxf(sqrtf(ss), EPSN);
    if (act) {
        float4 nv = make_float4(acc.x*invn, acc.y*invn, acc.z*invn, acc.w*invn);
        *(float4*)(g_x + (size_t)gw*EMB + lane*4) = nv;
        float4 f = *(const float4*)(g_final + (size_t)gw*EMB + lane*4);
        f.x += nv.x; f.y += nv.y; f.z += nv.z; f.w += nv.w;
        *(float4*)(g_final + (size_t)gw*EMB + lane*4) = f;
    }
}

// ---------------- item_emb = final/3 ; item_n = l2norm ; bf16 ----------------
__global__ void k_item() {
    int gw = (blockIdx.x * blockDim.x + threadIdx.x) >> 5;
    int lane = threadIdx.x & 31;
    if (gw >= N_NODE) return;
    const float inv3 = 1.0f / 3.0f;
    float ss = 0.0f;
    float v[4];
    #pragma unroll
    for (int i = 0; i < 4; ++i) {
        int k = lane + 32*i;
        v[i] = (k < EMB) ? g_final[gw*EMB + k] * inv3 : 0.0f;
        ss += v[i]*v[i];
    }
    ss = warp_sum(ss);
    float invn = 1.0f / fmaxf(sqrtf(ss), EPSN);
    #pragma unroll
    for (int i = 0; i < 4; ++i) {
        int k = lane + 32*i;
        if (k < EMB) {
            float nv = v[i] * invn;
            g_item[gw*EMB + k]  = v[i];
            g_itemn[gw*EMB + k] = nv;
            g_bf16[(size_t)gw*KPAD + k] = __float2bfloat16(nv);
        }
    }
    if (lane < KPAD - EMB) g_bf16[(size_t)gw*KPAD + EMB + lane] = __float2bfloat16(0.0f);
}

// ---------------- session embedding ----------------
__global__ void k_sess(const int* __restrict__ rev, const float* __restrict__ slen,
                       const int* __restrict__ mask, const float* __restrict__ w1,
                       const float* __restrict__ w2, const float* __restrict__ glu1b) {
    __shared__ float sh_seq[SEQ*EMB];
    __shared__ float sh_hs[EMB];
    __shared__ float sh_hsg[EMB];
    __shared__ float sh_nh[EMB];
    __shared__ float sh4[4];
    int b = blockIdx.x, t = threadIdx.x;
    int wid = t >> 5, lane = t & 31;

    for (int idx = t; idx < SEQ*EMB; idx += 128) {
        int l = idx / EMB, k = idx - l*EMB;
        int id = rev[b*SEQ + l];
        sh_seq[idx] = (id == 0) ? 0.0f : g_item[(size_t)(id-1)*EMB + k];
    }
    __syncthreads();
    if (t < EMB) {
        float acc = 0.0f;
        for (int l = 0; l < SEQ; ++l) acc += sh_seq[l*EMB + t];
        sh_hs[t] = acc / slen[b];
    }
    __syncthreads();
    if (t < EMB) {
        float p0=0.f,p1=0.f,p2=0.f,p3=0.f;
        for (int j = 0; j < EMB; j += 4) {
            p0 += sh_hs[j]   * g_glu2T[j*EMB + t];
            p1 += sh_hs[j+1] * g_glu2T[(j+1)*EMB + t];
            p2 += sh_hs[j+2] * g_glu2T[(j+2)*EMB + t];
            p3 += sh_hs[j+3] * g_glu2T[(j+3)*EMB + t];
        }
        sh_hsg[t] = (p0+p1)+(p2+p3);
    }
    __syncthreads();

    float sess_k = 0.0f;
    for (int l = 0; l < SEQ; ++l) {
        if (t < EMB) {
            float p0 = g_posw[l*EMB + t], p1=0.f, p2=0.f, p3=0.f;
            const float* sq = sh_seq + l*EMB;
            for (int j = 0; j < EMB; j += 4) {
                p0 += sq[j]   * w1[(EMB+j)*EMB + t];
                p1 += sq[j+1] * w1[(EMB+j+1)*EMB + t];
                p2 += sq[j+2] * w1[(EMB+j+2)*EMB + t];
                p3 += sq[j+3] * w1[(EMB+j+3)*EMB + t];
            }
            sh_nh[t] = tanhf((p0+p1)+(p2+p3));
        }
        __syncthreads();
        float prod = 0.0f;
        if (t < EMB) {
            float p0 = sh_hsg[t] + glu1b[t], p1=0.f, p2=0.f, p3=0.f;
            for (int j = 0; j < EMB; j += 4) {
                p0 += sh_nh[j]   * g_glu1T[j*EMB + t];
                p1 += sh_nh[j+1] * g_glu1T[(j+1)*EMB + t];
                p2 += sh_nh[j+2] * g_glu1T[(j+2)*EMB + t];
                p3 += sh_nh[j+3] * g_glu1T[(j+3)*EMB + t];
            }
            float g = 1.0f / (1.0f + expf(-((p0+p1)+(p2+p3))));
            prod = g * w2[t];
        }
        float wsum = warp_sum(prod);
        if (lane == 0) sh4[wid] = wsum;
        __syncthreads();
        float beta = (sh4[0] + sh4[1] + sh4[2] + sh4[3]) * (float)mask[b*SEQ + l];
        if (t < EMB) sess_k += beta * sh_seq[l*EMB + t];
        __syncthreads();
    }
    if (t < EMB) g_sess[b*EMB + t] = sess_k;
}

// ---------------- sess = W_K * l2norm(sess) ----------------
__global__ void k_sess_norm() {
    int gw = (blockIdx.x * blockDim.x + threadIdx.x) >> 5;
    int lane = threadIdx.x & 31;
    if (gw >= BATCH) return;
    float ss = 0.0f;
    float v[4];
    #pragma unroll
    for (int i = 0; i < 4; ++i) {
        int k = lane + 32*i;
        v[i] = (k < EMB) ? g_sess[gw*EMB + k] : 0.0f;
        ss += v[i]*v[i];
    }
    ss = warp_sum(ss);
    float sc = W_KF / fmaxf(sqrtf(ss), EPSN);
    #pragma unroll
    for (int i = 0; i < 4; ++i) {
        int k = lane + 32*i;
        if (k < EMB) g_sessn[gw*EMB + k] = v[i] * sc;
    }
}

// ---------------- scores: 128 items x 64 sessions per block ----------------
#define SC_SMEM ((128*EMB + 64*EMB)*4)
__global__ __launch_bounds__(256) void k_scores(float* __restrict__ scores) {
    extern __shared__ float sm_sc[];
    float* its = sm_sc;             // [128][100]
    float* ses = sm_sc + 128*EMB;   // [64][100]
    int t = threadIdx.x;
    int nb = blockIdx.x * 128;
    int bb = blockIdx.y * 64;
    for (int i = t; i < 128*EMB; i += 256) {
        int item = nb + i / EMB;
        its[i] = (item < N_NODE) ? g_itemn[(size_t)nb*EMB + i] : 0.0f;
    }
    for (int i = t; i < 64*EMB; i += 256) ses[i] = g_sessn[(size_t)bb*EMB + i];
    __syncthreads();
    int ic = t & 31, sg = t >> 5;
    float acc[8][4];
    #pragma unroll
    for (int j = 0; j < 8; ++j)
        #pragma unroll
        for (int ii = 0; ii < 4; ++ii) acc[j][ii] = 0.0f;
    for (int k4 = 0; k4 < 25; ++k4) {
        float4 iv[4];
        #pragma unroll
        for (int ii = 0; ii < 4; ++ii)
            iv[ii] = *(const float4*)&its[(ic + 32*ii)*EMB + k4*4];
        #pragma unroll
        for (int j = 0; j < 8; ++j) {
            float4 sv = *(const float4*)&ses[(sg*8 + j)*EMB + k4*4];
            #pragma unroll
            for (int ii = 0; ii < 4; ++ii)
                acc[j][ii] += iv[ii].x*sv.x + iv[ii].y*sv.y + iv[ii].z*sv.z + iv[ii].w*sv.w;
        }
    }
    #pragma unroll
    for (int j = 0; j < 8; ++j) {
        int b = bb + sg*8 + j;
        #pragma unroll
        for (int ii = 0; ii < 4; ++ii) {
            int col = nb + ic + 32*ii;
            if (col < N_NODE) scores[(size_t)b * N_NODE + col] = acc[j][ii];
        }
    }
}

// ---------------- loss_item: online CE ----------------
__global__ void k_loss(const float* __restrict__ scores, const int* __restrict__ tar,
                       float* __restrict__ out0) {
    __shared__ float shm[256], shs[256];
    int b = blockIdx.x, t = threadIdx.x;
    const float* row = scores + (size_t)b * N_NODE;
    float m = -INFINITY, s = 0.0f;
    for (int i = t; i < N_NODE; i += 256) {
        float v = row[i];
        if (v > m) { s = s * expf(m - v) + 1.0f; m = v; }
        else       { s += expf(v - m); }
    }
    shm[t] = m; shs[t] = s; __syncthreads();
    for (int o = 128; o > 0; o >>= 1) {
        if (t < o) {
            float m2 = shm[t+o], s2 = shs[t+o];
            float M = fmaxf(shm[t], m2);
            shs[t] = shs[t]*expf(shm[t]-M) + s2*expf(m2-M);
            shm[t] = M;
        }
        __syncthreads();
    }
    if (t == 0) {
        float lse = shm[0] + logf(shs[0]);
        atomicAdd(out0, (lse - row[tar[b]]) * (1.0f / BATCH));
    }
}

// ---------------- cl GEMM: mma.sync persistent, 4 warps x 32 rows, fused top-10 ----------------
__global__ __launch_bounds__(128) void k_cl_tc() {
    extern __shared__ __align__(16) char smraw[];   // A 30720 | B0 15360 | B1 15360
    __shared__ int sh_item;
    uint32_t sbase = (uint32_t)__cvta_generic_to_shared(smraw);
    int t = threadIdx.x, lane = t & 31, w = t >> 5;

    for (;;) {
        __syncthreads();
        if (t == 0) sh_item = atomicAdd(&g_work, 1);
        __syncthreads();
        int item = sh_item;
        if (item >= NITEMS) return;
        int rowblk = item >> 3, q = item & 7;
        int rbase = rowblk * CLM;
        int qs = (q * NTILES) / NQ, qe = ((q + 1) * NTILES) / NQ;

        // stage A tile: 128 rows x 112 halves
        const __nv_bfloat16* Ag = g_bf16 + (size_t)rbase * KPAD;
        for (int idx = t; idx < CLM*14; idx += 128) {
            int r = idx / 14, c = idx - r*14;
            *(uint4*)(smraw + (r*BROW + c*8)*2) = *(const uint4*)(Ag + r*KPAD + c*8);
        }
        __syncthreads();

        // A fragments: warp w owns rows w*32..w*32+31; two m16 halves
        uint32_t Af[KC][2][4];
        #pragma unroll
        for (int mh = 0; mh < 2; ++mh) {
            uint32_t aaddr = sbase +
                ((unsigned)(w*32 + mh*16 + (lane & 15))*BROW + ((lane >> 4)*8)) * 2;
            #pragma unroll
            for (int kc = 0; kc < KC; ++kc) {
                asm volatile("ldmatrix.sync.aligned.m8n8.x4.shared.b16 {%0,%1,%2,%3}, [%4];"
                    : "=r"(Af[kc][mh][0]), "=r"(Af[kc][mh][1]),
                      "=r"(Af[kc][mh][2]), "=r"(Af[kc][mh][3])
                    : "r"(aaddr + kc*32));
            }
        }
        __syncthreads();

        // prologue: async-load first B tile
        {
            const __nv_bfloat16* Bg = g_bf16 + (size_t)qs * CLN * KPAD;
            uint32_t dst = sbase + A_BYTES + (uint32_t)(qs & 1) * B_BYTES;
            for (int idx = t; idx < CLN*14; idx += 128) {
                int r = idx / 14, c = idx - r*14;
                uint32_t d = dst + (unsigned)(r*BROW + c*8)*2;
                const void* s = Bg + r*KPAD + c*8;
                asm volatile("cp.async.cg.shared.global [%0], [%1], 16;" :: "r"(d), "l"(s));
            }
            asm volatile("cp.async.commit_group;" ::: "memory");
        }

        // 4 top-10 lists: rows w*32 + mh*16 + (lane>>2) + half*8
        float tk0[TOPK], tk1[TOPK], tk2[TOPK], tk3[TOPK];
        #pragma unroll
        for (int i = 0; i < TOPK; ++i) {
            tk0[i] = -INFINITY; tk1[i] = -INFINITY;
            tk2[i] = -INFINITY; tk3[i] = -INFINITY;
        }

        int quad = lane >> 3, r8 = lane & 7;
        uint32_t bth = ((unsigned)(r8 + 8*(quad >> 1))*BROW + (quad & 1)*8) * 2;

        for (int tile = qs; tile < qe; ++tile) {
            asm volatile("cp.async.wait_group 0;" ::: "memory");
            __syncthreads();
            if (tile + 1 < qe) {
                const __nv_bfloat16* Bg = g_bf16 + (size_t)(tile + 1) * CLN * KPAD;
                uint32_t dst = sbase + A_BYTES + (uint32_t)((tile + 1) & 1) * B_BYTES;
                for (int idx = t; idx < CLN*14; idx += 128) {
                    int r = idx / 14, c = idx - r*14;
                    uint32_t d = dst + (unsigned)(r*BROW + c*8)*2;
                    const void* s = Bg + r*KPAD + c*8;
                    asm volatile("cp.async.cg.shared.global [%0], [%1], 16;" :: "r"(d), "l"(s));
                }
                asm volatile("cp.async.commit_group;" ::: "memory");
            }
            uint32_t bb = sbase + A_BYTES + (uint32_t)(tile & 1)*B_BYTES + bth;
            int npairs = (tile == NTILES-1) ? 2 : 4;
            for (int p = 0; p < npairs; ++p) {
                uint32_t ba = bb + (unsigned)p*(16*BROW*2);
                // load B fragments once per p (shared by both m-halves)
                uint32_t Bf[KC][4];
                #pragma unroll
                for (int kc = 0; kc < KC; ++kc) {
                    asm volatile("ldmatrix.sync.aligned.m8n8.x4.shared.b16 {%0,%1,%2,%3}, [%4];"
                        : "=r"(Bf[kc][0]), "=r"(Bf[kc][1]), "=r"(Bf[kc][2]), "=r"(Bf[kc][3])
                        : "r"(ba + kc*32));
                }
                #pragma unroll
                for (int mh = 0; mh < 2; ++mh) {
                    float d0[4] = {0.f,0.f,0.f,0.f}, d1[4] = {0.f,0.f,0.f,0.f};
                    #pragma unroll
                    for (int kc = 0; kc < KC; ++kc) {
                        asm volatile("mma.sync.aligned.m16n8k16.row.col.f32.bf16.bf16.f32 "
                            "{%0,%1,%2,%3}, {%4,%5,%6,%7}, {%8,%9}, {%0,%1,%2,%3};"
                            : "+f"(d0[0]), "+f"(d0[1]), "+f"(d0[2]), "+f"(d0[3])
                            : "r"(Af[kc][mh][0]), "r"(Af[kc][mh][1]),
                              "r"(Af[kc][mh][2]), "r"(Af[kc][mh][3]),
                              "r"(Bf[kc][0]), "r"(Bf[kc][1]));
                        asm volatile("mma.sync.aligned.m16n8k16.row.col.f32.bf16.bf16.f32 "
                            "{%0,%1,%2,%3}, {%4,%5,%6,%7}, {%8,%9}, {%0,%1,%2,%3};"
                            : "+f"(d1[0]), "+f"(d1[1]), "+f"(d1[2]), "+f"(d1[3])
                            : "r"(Af[kc][mh][0]), "r"(Af[kc][mh][1]),
                              "r"(Af[kc][mh][2]), "r"(Af[kc][mh][3]),
                              "r"(Bf[kc][2]), "r"(Bf[kc][3]));
                    }
                    if (mh == 0) {
                        topk_insert(tk0, d0[0]*INV_TEMP); topk_insert(tk0, d0[1]*INV_TEMP);
                        topk_insert(tk1, d0[2]*INV_TEMP); topk_insert(tk1, d0[3]*INV_TEMP);
                        topk_insert(tk0, d1[0]*INV_TEMP); topk_insert(tk0, d1[1]*INV_TEMP);
                        topk_insert(tk1, d1[2]*INV_TEMP); topk_insert(tk1, d1[3]*INV_TEMP);
                    } else {
                        topk_insert(tk2, d0[0]*INV_TEMP); topk_insert(tk2, d0[1]*INV_TEMP);
                        topk_insert(tk3, d0[2]*INV_TEMP); topk_insert(tk3, d0[3]*INV_TEMP);
                        topk_insert(tk2, d1[0]*INV_TEMP); topk_insert(tk2, d1[1]*INV_TEMP);
                        topk_insert(tk3, d1[2]*INV_TEMP); topk_insert(tk3, d1[3]*INV_TEMP);
                    }
                }
            }
        }

        // merge: 4 thread-local lists per row (lane&3) via smem [128][40]
        __syncthreads();
        float* mg = (float*)smraw;
        int g = lane >> 2, i4 = lane & 3;
        int base_r = w*32 + g;
        #pragma unroll
        for (int qq = 0; qq < TOPK; ++qq) {
            mg[(base_r     )*40 + i4*TOPK + qq] = tk0[qq];
            mg[(base_r + 8 )*40 + i4*TOPK + qq] = tk1[qq];
            mg[(base_r + 16)*40 + i4*TOPK + qq] = tk2[qq];
            mg[(base_r + 24)*40 + i4*TOPK + qq] = tk3[qq];
        }
        __syncthreads();
        {
            int row = rbase + t;
            if (row < N_NODE) {
                float m[TOPK];
                #pragma unroll
                for (int qq = 0; qq < TOPK; ++qq) m[qq] = -INFINITY;
                for (int qq = 0; qq < 4*TOPK; ++qq) topk_insert(m, mg[t*40 + qq]);
                #pragma unroll
                for (int qq = 0; qq < TOPK; ++qq)
                    g_qtk[((size_t)row*NQ + q)*TOPK + qq] = m[qq];
            }
        }
    }
}

// ---------------- cl merge ----------------
__global__ void k_cl_merge(float* __restrict__ out_cl) {
    __shared__ float sh[256];
    int idx = blockIdx.x * 256 + threadIdx.x;
    float contrib = 0.0f;
    if (idx < N_NODE) {
        float m[TOPK];
        #pragma unroll
        for (int q = 0; q < TOPK; ++q) m[q] = -INFINITY;
        const float* p = g_qtk + (size_t)idx*NQ*TOPK;
        for (int q = 0; q < NQ*TOPK; ++q) topk_insert(m, p[q]);
        float se = 0.0f;
        #pragma unroll
        for (int q = 1; q < TOPK; ++q) se += expf(m[q] - m[0]);
        contrib = log1pf(se) * (CL_WF / (float)N_NODE);
    }
    sh[threadIdx.x] = contrib; __syncthreads();
    for (int s = 128; s > 0; s >>= 1) {
        if (threadIdx.x < s) sh[threadIdx.x] += sh[threadIdx.x + s];
        __syncthreads();
    }
    if (threadIdx.x == 0) atomicAdd(out_cl, sh[0]);
}

// ---------------- launch ----------------
extern "C" void kernel_launch(void* const* d_in, const int* in_sizes, int n_in,
                              void* d_out, int out_size) {
    const float* slen  = (const float*)d_in[1];
    const int*   rev   = (const int*)d_in[2];
    const int*   mask  = (const int*)d_in[3];
    const int*   tar   = (const int*)d_in[5];
    const int*   arow  = (const int*)d_in[8];
    const int*   acol  = (const int*)d_in[9];
    const float* avals = (const float*)d_in[10];
    const float* emb   = (const float*)d_in[11];
    const float* pos   = (const float*)d_in[12];
    const float* witem = (const float*)d_in[13];
    const float* attw  = (const float*)d_in[14];
    const float* attb  = (const float*)d_in[15];
    const float* w1    = (const float*)d_in[16];
    const float* w2    = (const float*)d_in[17];
    const float* glu1  = (const float*)d_in[18];
    const float* glu1b = (const float*)d_in[19];
    const float* glu2  = (const float*)d_in[20];
    float* out = (float*)d_out;
    int E = in_sizes[8];

    cudaFuncSetAttribute(k_cl_tc, cudaFuncAttributeMaxDynamicSharedMemorySize, CL_SMEM);
    cudaFuncSetAttribute(k_scores, cudaFuncAttributeMaxDynamicSharedMemorySize, SC_SMEM);
    cudaFuncSetAttribute(k_lin_att, cudaFuncAttributeMaxDynamicSharedMemorySize,
                         (EMB*EMB + 64*EMB)*4);

    k_init<<<2048, 256>>>(emb, out, out_size);
    k_transpose<<<(N_LAYERS*EMB*EMB + 255)/256, 256>>>(witem, glu1, glu2);
    k_posw<<<SEQ, 128>>>(pos, w1);
    k_prep<<<(E + 255)/256, 256>>>(arow, acol, avals, E);
    k_scan<<<1, 1024>>>();
    k_scatter<<<(E + 255)/256, 256>>>(arow, acol, avals, E);

    for (int l = 0; l < N_LAYERS; ++l) {
        k_att_score<<<(N_NODE*32 + 255)/256, 256>>>(attw, attb);
        k_softmax_reduce<<<1, 1024>>>();
        k_lin_att<<<(N_NODE + 63)/64, 256, (EMB*EMB + 64*EMB)*4>>>(l);
        k_spmm_csr<<<(N_NODE*32 + 255)/256, 256>>>();
    }

    k_item<<<(N_NODE*32 + 255)/256, 256>>>();
    k_sess<<<BATCH, 128>>>(rev, slen, mask, w1, w2, glu1b);
    k_sess_norm<<<(BATCH*32 + 255)/256, 256>>>();

    dim3 sg((N_NODE + 127)/128, BATCH/64);
    k_scores<<<sg, 256, SC_SMEM>>>(out + 1);

    k_loss<<<BATCH, 256>>>(out + 1, tar, out);
    k_cl_tc<<<CLGRID, 128, CL_SMEM>>>();
    k_cl_merge<<<(N_NODE + 255)/256, 256>>>(out + out_size - 1);
}